// round 5
// baseline (speedup 1.0000x reference)
#include <cuda_runtime.h>
#include <cuda_bf16.h>
#include <cstdint>

// Model constants
#define D_MODEL 128
#define VOCAB   4096
#define N_LAYERS 4
#define D_FF    512
#define D_INNER 256
#define D_STATE 16
#define D_CONV  4
#define DT_RANK 8
#define BB      8
#define LL      4096
#define NTOK    (BB*LL)   // 32768

// ---------------- scratch (device globals: no allocations allowed) ----------
__device__ float g_x [NTOK * D_MODEL];     // 16 MB (layer input / output)
__device__ float g_ln[NTOK * D_MODEL];     // 16 MB
__device__ float g_xz[NTOK * 2*D_INNER];   // 64 MB (xc | z)
__device__ float g_u [NTOK * D_INNER];     // 32 MB
__device__ float g_db[NTOK * 40];          // 5.2 MB (dt_r | B | C)
__device__ float g_dt[NTOK * D_INNER];     // 32 MB
__device__ float g_y [NTOK * D_INNER];     // 32 MB
__device__ float g_h1[NTOK * D_FF];        // 64 MB

// ---------------- embedding gather ----------------
__global__ void embed_kernel(const int* __restrict__ tokens,
                             const float* __restrict__ emb,
                             float* __restrict__ x) {
    int idx = blockIdx.x * blockDim.x + threadIdx.x;   // NTOK*32 float4 slots
    int tok = idx >> 5;
    int j   = idx & 31;
    int t = tokens[tok];
    ((float4*)x)[idx] = ((const float4*)emb)[t * 32 + j];
}

// ---------------- LayerNorm (warp per row of 128) ----------------
__global__ void ln_kernel(const float* __restrict__ x,
                          const float* __restrict__ w,
                          const float* __restrict__ b,
                          float* __restrict__ out) {
    int row  = blockIdx.x * blockDim.y + threadIdx.y;
    int lane = threadIdx.x;
    const float4* xr = (const float4*)(x + (size_t)row * D_MODEL);
    float4 v = xr[lane];
    float s = v.x + v.y + v.z + v.w;
    #pragma unroll
    for (int o = 16; o; o >>= 1) s += __shfl_xor_sync(0xffffffffu, s, o);
    float mu = s * (1.0f / 128.0f);
    float d0 = v.x - mu, d1 = v.y - mu, d2 = v.z - mu, d3 = v.w - mu;
    float vs = d0*d0 + d1*d1 + d2*d2 + d3*d3;
    #pragma unroll
    for (int o = 16; o; o >>= 1) vs += __shfl_xor_sync(0xffffffffu, vs, o);
    float inv = rsqrtf(vs * (1.0f / 128.0f) + 1e-5f);
    float4 wv = ((const float4*)w)[lane];
    float4 bv = ((const float4*)b)[lane];
    float4 o;
    o.x = d0 * inv * wv.x + bv.x;
    o.y = d1 * inv * wv.y + bv.y;
    o.z = d2 * inv * wv.z + bv.z;
    o.w = d3 * inv * wv.w + bv.w;
    ((float4*)(out + (size_t)row * D_MODEL))[lane] = o;
}

// ---------------- generic SMEM-tiled fp32 GEMM:  C = act(A[MxK] @ B[KxN] + bias)
#define GBM 64
#define GBN 64
#define GBK 16
__global__ void gemm_kernel(const float* __restrict__ A,
                            const float* __restrict__ B,
                            const float* __restrict__ bias,
                            float* __restrict__ C,
                            int M, int N, int K, int act) {
    __shared__ float As[GBK][GBM];
    __shared__ float Bs[GBK][GBN + 4];
    int tid = threadIdx.x;
    int tm = tid >> 4, tn = tid & 15;
    int row0 = blockIdx.y * GBM;
    int col0 = blockIdx.x * GBN;
    float acc[4][4] = {};
    for (int k0 = 0; k0 < K; k0 += GBK) {
        #pragma unroll
        for (int i = tid; i < GBM * GBK; i += 256) {
            int m = i >> 4, kk = i & 15;
            int gm = row0 + m, gk = k0 + kk;
            As[kk][m] = (gm < M && gk < K) ? A[(size_t)gm * K + gk] : 0.0f;
        }
        #pragma unroll
        for (int i = tid; i < GBK * GBN; i += 256) {
            int kk = i >> 6, n = i & 63;
            int gk = k0 + kk, gn = col0 + n;
            Bs[kk][n] = (gk < K && gn < N) ? B[(size_t)gk * N + gn] : 0.0f;
        }
        __syncthreads();
        #pragma unroll
        for (int kk = 0; kk < GBK; kk++) {
            float a[4], bb[4];
            #pragma unroll
            for (int i = 0; i < 4; i++) a[i] = As[kk][tm * 4 + i];
            #pragma unroll
            for (int j = 0; j < 4; j++) bb[j] = Bs[kk][tn * 4 + j];
            #pragma unroll
            for (int i = 0; i < 4; i++)
                #pragma unroll
                for (int j = 0; j < 4; j++)
                    acc[i][j] = fmaf(a[i], bb[j], acc[i][j]);
        }
        __syncthreads();
    }
    #pragma unroll
    for (int i = 0; i < 4; i++) {
        int gm = row0 + tm * 4 + i;
        if (gm >= M) continue;
        #pragma unroll
        for (int j = 0; j < 4; j++) {
            int gn = col0 + tn * 4 + j;
            if (gn >= N) continue;
            float v = acc[i][j];
            if (bias) v += bias[gn];
            if (act == 1) v = fmaxf(v, 0.0f);
            C[(size_t)gm * N + gn] = v;
        }
    }
}

// ---------------- depthwise causal conv (k=4) + SiLU ----------------
__global__ void conv_silu_kernel(const float* __restrict__ xz,
                                 const float* __restrict__ cw,
                                 const float* __restrict__ cb,
                                 float* __restrict__ u) {
    int idx = blockIdx.x * blockDim.x + threadIdx.x;  // tok*256 + d
    int d   = idx & (D_INNER - 1);
    int tok = idx >> 8;
    int l   = tok & (LL - 1);
    float acc = cb[d];
    #pragma unroll
    for (int j = 0; j < 4; j++) {
        int tl = l - 3 + j;
        if (tl >= 0)
            acc = fmaf(cw[d * 4 + j], xz[(size_t)(tok - 3 + j) * (2*D_INNER) + d], acc);
    }
    u[idx] = acc / (1.0f + __expf(-acc));  // silu
}

// ---------------- dt = softplus(dt_r @ W_dt + b_dt)  (K=8 fused) ----------------
__global__ void dt_kernel(const float* __restrict__ dbc,
                          const float* __restrict__ Wdt,
                          const float* __restrict__ bdt,
                          float* __restrict__ dt) {
    int idx = blockIdx.x * blockDim.x + threadIdx.x;  // tok*256 + d
    int d   = idx & (D_INNER - 1);
    int tok = idx >> 8;
    const float* r = dbc + (size_t)tok * 40;
    float s = bdt[d];
    #pragma unroll
    for (int j = 0; j < 8; j++)
        s = fmaf(r[j], Wdt[j * D_INNER + d], s);
    dt[idx] = (s > 20.0f) ? s : log1pf(__expf(s));
}

// ---------------- selective scan (fused with +u*D and *silu(z)) ----------------
// thread = (channel_local, state); block = 16 channels of one batch; 256 threads
#define SCHUNK 64
__global__ void scan_kernel(const float* __restrict__ dt,
                            const float* __restrict__ u,
                            const float* __restrict__ dbc,
                            const float* __restrict__ xz,
                            const float* __restrict__ A_log,
                            const float* __restrict__ Dskip,
                            float* __restrict__ ybuf) {
    __shared__ float sB [SCHUNK][16];
    __shared__ float sC [SCHUNK][16];
    __shared__ float sdt[SCHUNK][16];
    __shared__ float su [SCHUNK][16];
    __shared__ float sz [SCHUNK][16];
    __shared__ float sy [SCHUNK][16];
    int b   = blockIdx.x >> 4;
    int ch0 = (blockIdx.x & 15) * 16;
    int tid = threadIdx.x;
    int cl  = tid >> 4;
    int s   = tid & 15;
    int ch  = ch0 + cl;
    float A  = -__expf(A_log[ch * D_STATE + s]);
    float Ds = Dskip[ch];
    float h = 0.0f;
    size_t base_tok = (size_t)b * LL;
    for (int t0 = 0; t0 < LL; t0 += SCHUNK) {
        for (int i = tid; i < SCHUNK * 16; i += 256) {
            int st = i >> 4, j = i & 15;
            size_t tok = base_tok + t0 + st;
            sB [st][j] = dbc[tok * 40 + 8  + j];
            sC [st][j] = dbc[tok * 40 + 24 + j];
            sdt[st][j] = dt [tok * D_INNER + ch0 + j];
            su [st][j] = u  [tok * D_INNER + ch0 + j];
            sz [st][j] = xz [tok * (2*D_INNER) + D_INNER + ch0 + j];
        }
        __syncthreads();
        #pragma unroll 4
        for (int i = 0; i < SCHUNK; i++) {
            float dtv = sdt[i][cl];
            float uv  = su [i][cl];
            float dA  = __expf(dtv * A);
            h = fmaf(dA, h, dtv * uv * sB[i][s]);
            float p = h * sC[i][s];
            p += __shfl_xor_sync(0xffffffffu, p, 8);
            p += __shfl_xor_sync(0xffffffffu, p, 4);
            p += __shfl_xor_sync(0xffffffffu, p, 2);
            p += __shfl_xor_sync(0xffffffffu, p, 1);
            if (s == 0) {
                float zv = sz[i][cl];
                float yv = p + uv * Ds;
                yv *= zv / (1.0f + __expf(-zv));  // * silu(z)
                sy[i][cl] = yv;
            }
        }
        __syncthreads();
        for (int i = tid; i < SCHUNK * 16; i += 256) {
            int st = i >> 4, j = i & 15;
            ybuf[(base_tok + t0 + st) * D_INNER + ch0 + j] = sy[st][j];
        }
        __syncthreads();
    }
}

// ---------------- host launcher ----------------
extern "C" void kernel_launch(void* const* d_in, const int* in_sizes, int n_in,
                              void* d_out, int out_size) {
    const int*   tokens  = (const int*)  d_in[0];
    const float* emb     = (const float*)d_in[1];
    const float* ln_w    = (const float*)d_in[2];
    const float* ln_b    = (const float*)d_in[3];
    const float* W_in    = (const float*)d_in[4];
    const float* conv_w  = (const float*)d_in[5];
    const float* conv_b  = (const float*)d_in[6];
    const float* W_xproj = (const float*)d_in[7];
    const float* W_dt    = (const float*)d_in[8];
    const float* b_dt    = (const float*)d_in[9];
    const float* A_log   = (const float*)d_in[10];
    const float* D_skip  = (const float*)d_in[11];
    const float* W_out   = (const float*)d_in[12];
    const float* W1      = (const float*)d_in[13];
    const float* b1      = (const float*)d_in[14];
    const float* W2      = (const float*)d_in[15];
    const float* b2      = (const float*)d_in[16];
    float* out = (float*)d_out;

    float *x, *ln, *xz, *u, *dbc, *dt, *y, *h1;
    cudaGetSymbolAddress((void**)&x,   g_x);
    cudaGetSymbolAddress((void**)&ln,  g_ln);
    cudaGetSymbolAddress((void**)&xz,  g_xz);
    cudaGetSymbolAddress((void**)&u,   g_u);
    cudaGetSymbolAddress((void**)&dbc, g_db);
    cudaGetSymbolAddress((void**)&dt,  g_dt);
    cudaGetSymbolAddress((void**)&y,   g_y);
    cudaGetSymbolAddress((void**)&h1,  g_h1);

    // embedding gather: NTOK*32 float4
    embed_kernel<<<(NTOK * 32) / 256, 256>>>(tokens, emb, x);

    for (int l = 0; l < N_LAYERS; l++) {
        const float* lw  = ln_w    + l * D_MODEL;
        const float* lb  = ln_b    + l * D_MODEL;
        const float* wi  = W_in    + (size_t)l * D_MODEL * 2 * D_INNER;
        const float* cw  = conv_w  + (size_t)l * D_INNER * D_CONV;
        const float* cb  = conv_b  + (size_t)l * D_INNER;
        const float* wx  = W_xproj + (size_t)l * D_INNER * 40;
        const float* wd  = W_dt    + (size_t)l * DT_RANK * D_INNER;
        const float* bd  = b_dt    + (size_t)l * D_INNER;
        const float* al  = A_log   + (size_t)l * D_INNER * D_STATE;
        const float* dsk = D_skip  + (size_t)l * D_INNER;
        const float* wo  = W_out   + (size_t)l * D_INNER * D_MODEL;

        ln_kernel<<<NTOK / 8, dim3(32, 8)>>>(x, lw, lb, ln);
        // xz = ln @ W_in  [32768 x 512]
        gemm_kernel<<<dim3(512 / GBN, NTOK / GBM), 256>>>(ln, wi, nullptr, xz,
                                                          NTOK, 512, 128, 0);
        conv_silu_kernel<<<NTOK * D_INNER / 256, 256>>>(xz, cw, cb, u);
        // dbc = u @ W_xproj  [32768 x 40]
        gemm_kernel<<<dim3(1, NTOK / GBM), 256>>>(u, wx, nullptr, dbc,
                                                  NTOK, 40, 256, 0);
        dt_kernel<<<NTOK * D_INNER / 256, 256>>>(dbc, wd, bd, dt);
        scan_kernel<<<BB * 16, 256>>>(dt, u, dbc, xz, al, dsk, y);
        // x = y @ W_out  [32768 x 128]
        gemm_kernel<<<dim3(128 / GBN, NTOK / GBM), 256>>>(y, wo, nullptr, x,
                                                          NTOK, 128, 256, 0);
    }

    // h1 = relu(x @ W1 + b1)  [32768 x 512]
    gemm_kernel<<<dim3(512 / GBN, NTOK / GBM), 256>>>(x, W1, b1, h1,
                                                      NTOK, D_FF, D_MODEL, 1);
    // out = h1 @ W2 + b2  [32768 x 4096]
    gemm_kernel<<<dim3(VOCAB / GBN, NTOK / GBM), 256>>>(h1, W2, b2, out,
                                                        NTOK, VOCAB, D_FF, 0);
}

// round 9
// speedup vs baseline: 1.6770x; 1.6770x over previous
#include <cuda_runtime.h>
#include <cuda_bf16.h>
#include <cstdint>

// Model constants
#define D_MODEL 128
#define VOCAB   4096
#define N_LAYERS 4
#define D_FF    512
#define D_INNER 256
#define D_STATE 16
#define D_CONV  4
#define DT_RANK 8
#define BB      8
#define LL      4096
#define NTOK    (BB*LL)   // 32768

// ---------------- scratch (device globals: no allocations allowed) ----------
__device__ float g_x [NTOK * D_MODEL];
__device__ float g_ln[NTOK * D_MODEL];
__device__ float g_xz[NTOK * 2*D_INNER];
__device__ float g_u [NTOK * D_INNER];
__device__ float g_db[NTOK * 40];
__device__ float g_dt[NTOK * D_INNER];
__device__ float g_y [NTOK * D_INNER];
__device__ float g_h1[NTOK * D_FF];

// ---------------- embedding gather ----------------
__global__ void embed_kernel(const int* __restrict__ tokens,
                             const float* __restrict__ emb,
                             float* __restrict__ x) {
    int idx = blockIdx.x * blockDim.x + threadIdx.x;
    int tok = idx >> 5;
    int j   = idx & 31;
    int t = tokens[tok];
    ((float4*)x)[idx] = ((const float4*)emb)[t * 32 + j];
}

// ---------------- LayerNorm (warp per row of 128) ----------------
__global__ void ln_kernel(const float* __restrict__ x,
                          const float* __restrict__ w,
                          const float* __restrict__ b,
                          float* __restrict__ out) {
    int row  = blockIdx.x * blockDim.y + threadIdx.y;
    int lane = threadIdx.x;
    const float4* xr = (const float4*)(x + (size_t)row * D_MODEL);
    float4 v = xr[lane];
    float s = v.x + v.y + v.z + v.w;
    #pragma unroll
    for (int o = 16; o; o >>= 1) s += __shfl_xor_sync(0xffffffffu, s, o);
    float mu = s * (1.0f / 128.0f);
    float d0 = v.x - mu, d1 = v.y - mu, d2 = v.z - mu, d3 = v.w - mu;
    float vs = d0*d0 + d1*d1 + d2*d2 + d3*d3;
    #pragma unroll
    for (int o = 16; o; o >>= 1) vs += __shfl_xor_sync(0xffffffffu, vs, o);
    float inv = rsqrtf(vs * (1.0f / 128.0f) + 1e-5f);
    float4 wv = ((const float4*)w)[lane];
    float4 bv = ((const float4*)b)[lane];
    float4 o;
    o.x = d0 * inv * wv.x + bv.x;
    o.y = d1 * inv * wv.y + bv.y;
    o.z = d2 * inv * wv.z + bv.z;
    o.w = d3 * inv * wv.w + bv.w;
    ((float4*)(out + (size_t)row * D_MODEL))[lane] = o;
}

// ================= 3xTF32 tensor-core GEMM (fp32-accurate) =================
// C[MxN] = act(A[MxK] @ B[KxN] + bias). Requires M%128==0, N%128==0, K%32==0.
// Block = 256 threads (8 warps: 4 m-groups x 2 n-groups). Tile 128x128x32.
#define TBM 128
#define TBN 128
#define TBK 32
#define SA  (TBK + 4)
#define SBS (TBN + 4)
#define ASZ (TBM * SA)
#define BSZ (TBK * SBS)

__device__ __forceinline__ void cp_async16(void* smem, const void* gptr) {
    uint32_t s = (uint32_t)__cvta_generic_to_shared(smem);
    asm volatile("cp.async.cg.shared.global [%0], [%1], 16;\n" :: "r"(s), "l"(gptr));
}
// split x into tf32 hi + tf32 lo (error-compensated)
__device__ __forceinline__ void split_tf32(float x, uint32_t& hi, uint32_t& lo) {
    asm("cvt.rna.tf32.f32 %0, %1;" : "=r"(hi) : "f"(x));
    float r = x - __uint_as_float(hi);
    asm("cvt.rna.tf32.f32 %0, %1;" : "=r"(lo) : "f"(r));
}

#define MMA_TF32(d, a0,a1,a2,a3, b0,b1) \
    asm volatile("mma.sync.aligned.m16n8k8.row.col.f32.tf32.tf32.f32 " \
                 "{%0,%1,%2,%3},{%4,%5,%6,%7},{%8,%9},{%0,%1,%2,%3};\n" \
                 : "+f"(d[0]), "+f"(d[1]), "+f"(d[2]), "+f"(d[3]) \
                 : "r"(a0), "r"(a1), "r"(a2), "r"(a3), "r"(b0), "r"(b1))

__global__ __launch_bounds__(256, 1)
void mma_gemm_kernel(const float* __restrict__ A,
                     const float* __restrict__ B,
                     const float* __restrict__ bias,
                     float* __restrict__ C,
                     int M, int N, int K, int act) {
    extern __shared__ float smem[];
    float* As = smem;              // [2][TBM][SA]
    float* Bs = smem + 2 * ASZ;    // [2][TBK][SBS]

    int tid  = threadIdx.x;
    int lane = tid & 31;
    int wid  = tid >> 5;
    int warp_m = wid & 3;
    int warp_n = wid >> 2;
    int row0 = blockIdx.y * TBM;
    int col0 = blockIdx.x * TBN;

    float acc[2][8][4];
    #pragma unroll
    for (int i = 0; i < 2; i++)
        #pragma unroll
        for (int j = 0; j < 8; j++)
            #pragma unroll
            for (int k = 0; k < 4; k++) acc[i][j][k] = 0.0f;

    int nIter = K / TBK;

    auto load_tiles = [&](int it, int stage) {
        int k0 = it * TBK;
        float* as = As + stage * ASZ;
        float* bs = Bs + stage * BSZ;
        #pragma unroll
        for (int j = 0; j < 4; j++) {
            int id  = tid + j * 256;
            int r   = id >> 3;
            int c   = (id & 7) * 4;
            cp_async16(&as[r * SA + c], &A[(size_t)(row0 + r) * K + k0 + c]);
        }
        #pragma unroll
        for (int j = 0; j < 4; j++) {
            int id  = tid + j * 256;
            int r   = id >> 5;
            int c   = (id & 31) * 4;
            cp_async16(&bs[r * SBS + c], &B[(size_t)(k0 + r) * N + col0 + c]);
        }
        asm volatile("cp.async.commit_group;\n");
    };

    load_tiles(0, 0);

    for (int it = 0; it < nIter; it++) {
        if (it + 1 < nIter) {
            load_tiles(it + 1, (it + 1) & 1);
            asm volatile("cp.async.wait_group 1;\n");
        } else {
            asm volatile("cp.async.wait_group 0;\n");
        }
        __syncthreads();

        const float* as = As + (it & 1) * ASZ;
        const float* bs = Bs + (it & 1) * BSZ;

        #pragma unroll
        for (int kk = 0; kk < 4; kk++) {
            // A fragments: hi/lo split
            uint32_t uah[2][4], ual[2][4];
            #pragma unroll
            for (int mi = 0; mi < 2; mi++) {
                int r = warp_m * 32 + mi * 16 + (lane >> 2);
                int c = kk * 8 + (lane & 3);
                split_tf32(as[r * SA + c],           uah[mi][0], ual[mi][0]);
                split_tf32(as[(r + 8) * SA + c],     uah[mi][1], ual[mi][1]);
                split_tf32(as[r * SA + c + 4],       uah[mi][2], ual[mi][2]);
                split_tf32(as[(r + 8) * SA + c + 4], uah[mi][3], ual[mi][3]);
            }
            #pragma unroll
            for (int ni = 0; ni < 8; ni++) {
                int br = kk * 8 + (lane & 3);
                int bc = warp_n * 64 + ni * 8 + (lane >> 2);
                uint32_t bh0, bl0, bh1, bl1;
                split_tf32(bs[br * SBS + bc],       bh0, bl0);
                split_tf32(bs[(br + 4) * SBS + bc], bh1, bl1);
                #pragma unroll
                for (int mi = 0; mi < 2; mi++) {
                    // correction terms first, then main term
                    MMA_TF32(acc[mi][ni], uah[mi][0], uah[mi][1], uah[mi][2], uah[mi][3], bl0, bl1);
                    MMA_TF32(acc[mi][ni], ual[mi][0], ual[mi][1], ual[mi][2], ual[mi][3], bh0, bh1);
                    MMA_TF32(acc[mi][ni], uah[mi][0], uah[mi][1], uah[mi][2], uah[mi][3], bh0, bh1);
                }
            }
        }
        __syncthreads();
    }

    // epilogue
    #pragma unroll
    for (int mi = 0; mi < 2; mi++) {
        int r0 = row0 + warp_m * 32 + mi * 16 + (lane >> 2);
        #pragma unroll
        for (int ni = 0; ni < 8; ni++) {
            int c0 = col0 + warp_n * 64 + ni * 8 + (lane & 3) * 2;
            float b0 = 0.f, b1 = 0.f;
            if (bias) { b0 = bias[c0]; b1 = bias[c0 + 1]; }
            float v0 = acc[mi][ni][0] + b0;
            float v1 = acc[mi][ni][1] + b1;
            float v2 = acc[mi][ni][2] + b0;
            float v3 = acc[mi][ni][3] + b1;
            if (act == 1) {
                v0 = fmaxf(v0, 0.f); v1 = fmaxf(v1, 0.f);
                v2 = fmaxf(v2, 0.f); v3 = fmaxf(v3, 0.f);
            }
            *(float2*)&C[(size_t)r0 * N + c0]       = make_float2(v0, v1);
            *(float2*)&C[(size_t)(r0 + 8) * N + c0] = make_float2(v2, v3);
        }
    }
}
#define MMA_SMEM ((2 * ASZ + 2 * BSZ) * 4)

// ---------------- small fp32 GEMM (kept for xproj, N=40) ----------------
#define GBM 64
#define GBN 64
#define GBK 16
__global__ void gemm_kernel(const float* __restrict__ A,
                            const float* __restrict__ B,
                            const float* __restrict__ bias,
                            float* __restrict__ C,
                            int M, int N, int K, int act) {
    __shared__ float As[GBK][GBM];
    __shared__ float Bs[GBK][GBN + 4];
    int tid = threadIdx.x;
    int tm = tid >> 4, tn = tid & 15;
    int row0 = blockIdx.y * GBM;
    int col0 = blockIdx.x * GBN;
    float acc[4][4] = {};
    for (int k0 = 0; k0 < K; k0 += GBK) {
        #pragma unroll
        for (int i = tid; i < GBM * GBK; i += 256) {
            int m = i >> 4, kk = i & 15;
            int gm = row0 + m, gk = k0 + kk;
            As[kk][m] = (gm < M && gk < K) ? A[(size_t)gm * K + gk] : 0.0f;
        }
        #pragma unroll
        for (int i = tid; i < GBK * GBN; i += 256) {
            int kk = i >> 6, n = i & 63;
            int gk = k0 + kk, gn = col0 + n;
            Bs[kk][n] = (gk < K && gn < N) ? B[(size_t)gk * N + gn] : 0.0f;
        }
        __syncthreads();
        #pragma unroll
        for (int kk = 0; kk < GBK; kk++) {
            float a[4], bb[4];
            #pragma unroll
            for (int i = 0; i < 4; i++) a[i] = As[kk][tm * 4 + i];
            #pragma unroll
            for (int j = 0; j < 4; j++) bb[j] = Bs[kk][tn * 4 + j];
            #pragma unroll
            for (int i = 0; i < 4; i++)
                #pragma unroll
                for (int j = 0; j < 4; j++)
                    acc[i][j] = fmaf(a[i], bb[j], acc[i][j]);
        }
        __syncthreads();
    }
    #pragma unroll
    for (int i = 0; i < 4; i++) {
        int gm = row0 + tm * 4 + i;
        if (gm >= M) continue;
        #pragma unroll
        for (int j = 0; j < 4; j++) {
            int gn = col0 + tn * 4 + j;
            if (gn >= N) continue;
            float v = acc[i][j];
            if (bias) v += bias[gn];
            if (act == 1) v = fmaxf(v, 0.0f);
            C[(size_t)gm * N + gn] = v;
        }
    }
}

// ---------------- depthwise causal conv (k=4) + SiLU ----------------
__global__ void conv_silu_kernel(const float* __restrict__ xz,
                                 const float* __restrict__ cw,
                                 const float* __restrict__ cb,
                                 float* __restrict__ u) {
    int idx = blockIdx.x * blockDim.x + threadIdx.x;
    int d   = idx & (D_INNER - 1);
    int tok = idx >> 8;
    int l   = tok & (LL - 1);
    float acc = cb[d];
    #pragma unroll
    for (int j = 0; j < 4; j++) {
        int tl = l - 3 + j;
        if (tl >= 0)
            acc = fmaf(cw[d * 4 + j], xz[(size_t)(tok - 3 + j) * (2*D_INNER) + d], acc);
    }
    u[idx] = acc / (1.0f + __expf(-acc));
}

// ---------------- dt = softplus(dt_r @ W_dt + b_dt) ----------------
__global__ void dt_kernel(const float* __restrict__ dbc,
                          const float* __restrict__ Wdt,
                          const float* __restrict__ bdt,
                          float* __restrict__ dt) {
    int idx = blockIdx.x * blockDim.x + threadIdx.x;
    int d   = idx & (D_INNER - 1);
    int tok = idx >> 8;
    const float* r = dbc + (size_t)tok * 40;
    float s = bdt[d];
    #pragma unroll
    for (int j = 0; j < 8; j++)
        s = fmaf(r[j], Wdt[j * D_INNER + d], s);
    dt[idx] = (s > 20.0f) ? s : log1pf(__expf(s));
}

// ---------------- selective scan ----------------
#define SCHUNK 64
__global__ void scan_kernel(const float* __restrict__ dt,
                            const float* __restrict__ u,
                            const float* __restrict__ dbc,
                            const float* __restrict__ xz,
                            const float* __restrict__ A_log,
                            const float* __restrict__ Dskip,
                            float* __restrict__ ybuf) {
    __shared__ float sB [SCHUNK][16];
    __shared__ float sC [SCHUNK][16];
    __shared__ float sdt[SCHUNK][16];
    __shared__ float su [SCHUNK][16];
    __shared__ float sz [SCHUNK][16];
    __shared__ float sy [SCHUNK][16];
    int b   = blockIdx.x >> 4;
    int ch0 = (blockIdx.x & 15) * 16;
    int tid = threadIdx.x;
    int cl  = tid >> 4;
    int s   = tid & 15;
    int ch  = ch0 + cl;
    float A  = -__expf(A_log[ch * D_STATE + s]);
    float Ds = Dskip[ch];
    float h = 0.0f;
    size_t base_tok = (size_t)b * LL;
    for (int t0 = 0; t0 < LL; t0 += SCHUNK) {
        for (int i = tid; i < SCHUNK * 16; i += 256) {
            int st = i >> 4, j = i & 15;
            size_t tok = base_tok + t0 + st;
            sB [st][j] = dbc[tok * 40 + 8  + j];
            sC [st][j] = dbc[tok * 40 + 24 + j];
            sdt[st][j] = dt [tok * D_INNER + ch0 + j];
            su [st][j] = u  [tok * D_INNER + ch0 + j];
            sz [st][j] = xz [tok * (2*D_INNER) + D_INNER + ch0 + j];
        }
        __syncthreads();
        #pragma unroll 4
        for (int i = 0; i < SCHUNK; i++) {
            float dtv = sdt[i][cl];
            float uv  = su [i][cl];
            float dA  = __expf(dtv * A);
            h = fmaf(dA, h, dtv * uv * sB[i][s]);
            float p = h * sC[i][s];
            p += __shfl_xor_sync(0xffffffffu, p, 8);
            p += __shfl_xor_sync(0xffffffffu, p, 4);
            p += __shfl_xor_sync(0xffffffffu, p, 2);
            p += __shfl_xor_sync(0xffffffffu, p, 1);
            if (s == 0) {
                float zv = sz[i][cl];
                float yv = p + uv * Ds;
                yv *= zv / (1.0f + __expf(-zv));
                sy[i][cl] = yv;
            }
        }
        __syncthreads();
        for (int i = tid; i < SCHUNK * 16; i += 256) {
            int st = i >> 4, j = i & 15;
            ybuf[(base_tok + t0 + st) * D_INNER + ch0 + j] = sy[st][j];
        }
        __syncthreads();
    }
}

// ---------------- host launcher ----------------
extern "C" void kernel_launch(void* const* d_in, const int* in_sizes, int n_in,
                              void* d_out, int out_size) {
    const int*   tokens  = (const int*)  d_in[0];
    const float* emb     = (const float*)d_in[1];
    const float* ln_w    = (const float*)d_in[2];
    const float* ln_b    = (const float*)d_in[3];
    const float* W_in    = (const float*)d_in[4];
    const float* conv_w  = (const float*)d_in[5];
    const float* conv_b  = (const float*)d_in[6];
    const float* W_xproj = (const float*)d_in[7];
    const float* W_dt    = (const float*)d_in[8];
    const float* b_dt    = (const float*)d_in[9];
    const float* A_log   = (const float*)d_in[10];
    const float* D_skip  = (const float*)d_in[11];
    const float* W_out   = (const float*)d_in[12];
    const float* W1      = (const float*)d_in[13];
    const float* b1      = (const float*)d_in[14];
    const float* W2      = (const float*)d_in[15];
    const float* b2      = (const float*)d_in[16];
    float* out = (float*)d_out;

    float *x, *ln, *xz, *u, *dbc, *dt, *y, *h1;
    cudaGetSymbolAddress((void**)&x,   g_x);
    cudaGetSymbolAddress((void**)&ln,  g_ln);
    cudaGetSymbolAddress((void**)&xz,  g_xz);
    cudaGetSymbolAddress((void**)&u,   g_u);
    cudaGetSymbolAddress((void**)&dbc, g_db);
    cudaGetSymbolAddress((void**)&dt,  g_dt);
    cudaGetSymbolAddress((void**)&y,   g_y);
    cudaGetSymbolAddress((void**)&h1,  g_h1);

    cudaFuncSetAttribute(mma_gemm_kernel,
                         cudaFuncAttributeMaxDynamicSharedMemorySize, MMA_SMEM);

    embed_kernel<<<(NTOK * 32) / 256, 256>>>(tokens, emb, x);

    for (int l = 0; l < N_LAYERS; l++) {
        const float* lw  = ln_w    + l * D_MODEL;
        const float* lb  = ln_b    + l * D_MODEL;
        const float* wi  = W_in    + (size_t)l * D_MODEL * 2 * D_INNER;
        const float* cw  = conv_w  + (size_t)l * D_INNER * D_CONV;
        const float* cb  = conv_b  + (size_t)l * D_INNER;
        const float* wx  = W_xproj + (size_t)l * D_INNER * 40;
        const float* wd  = W_dt    + (size_t)l * DT_RANK * D_INNER;
        const float* bd  = b_dt    + (size_t)l * D_INNER;
        const float* al  = A_log   + (size_t)l * D_INNER * D_STATE;
        const float* dsk = D_skip  + (size_t)l * D_INNER;
        const float* wo  = W_out   + (size_t)l * D_INNER * D_MODEL;

        ln_kernel<<<NTOK / 8, dim3(32, 8)>>>(x, lw, lb, ln);
        // xz = ln @ W_in  [32768 x 512], K=128  (3xTF32 TC)
        mma_gemm_kernel<<<dim3(512 / TBN, NTOK / TBM), 256, MMA_SMEM>>>(
            ln, wi, nullptr, xz, NTOK, 512, 128, 0);
        conv_silu_kernel<<<NTOK * D_INNER / 256, 256>>>(xz, cw, cb, u);
        // dbc = u @ W_xproj  [32768 x 40], K=256  (fp32)
        gemm_kernel<<<dim3(1, NTOK / GBM), 256>>>(u, wx, nullptr, dbc,
                                                  NTOK, 40, 256, 0);
        dt_kernel<<<NTOK * D_INNER / 256, 256>>>(dbc, wd, bd, dt);
        scan_kernel<<<BB * 16, 256>>>(dt, u, dbc, xz, al, dsk, y);
        // x = y @ W_out  [32768 x 128], K=256  (3xTF32 TC)
        mma_gemm_kernel<<<dim3(128 / TBN, NTOK / TBM), 256, MMA_SMEM>>>(
            y, wo, nullptr, x, NTOK, 128, 256, 0);
    }

    // h1 = relu(x @ W1 + b1)  [32768 x 512], K=128  (3xTF32 TC)
    mma_gemm_kernel<<<dim3(512 / TBN, NTOK / TBM), 256, MMA_SMEM>>>(
        x, W1, b1, h1, NTOK, D_FF, D_MODEL, 1);
    // out = h1 @ W2 + b2  [32768 x 4096], K=512  (3xTF32 TC)
    mma_gemm_kernel<<<dim3(VOCAB / TBN, NTOK / TBM), 256, MMA_SMEM>>>(
        h1, W2, b2, out, NTOK, VOCAB, D_FF, 0);
}

// round 10
// speedup vs baseline: 2.0282x; 1.2094x over previous
#include <cuda_runtime.h>
#include <cuda_bf16.h>
#include <cstdint>

// Model constants
#define D_MODEL 128
#define VOCAB   4096
#define N_LAYERS 4
#define D_FF    512
#define D_INNER 256
#define D_STATE 16
#define D_CONV  4
#define DT_RANK 8
#define BB      8
#define LL      4096
#define NTOK    (BB*LL)   // 32768

// ---------------- scratch (device globals: no allocations allowed) ----------
__device__ float g_x [NTOK * D_MODEL];          // layer input / output
__device__ float g_xz[NTOK * 2*D_INNER];
__device__ float g_u [NTOK * D_INNER];
__device__ float g_db[NTOK * 40];
__device__ float g_dt[NTOK * D_INNER];
__device__ float g_h1[NTOK * D_FF];
// bf16 split buffers
__device__ __nv_bfloat16 g_ah[NTOK * D_FF];     // A hi (max 32768x512)
__device__ __nv_bfloat16 g_al[NTOK * D_FF];     // A lo
__device__ __nv_bfloat16 g_bh[VOCAB * D_FF];    // B hi, transposed [N][K] (max 4096x512)
__device__ __nv_bfloat16 g_bl[VOCAB * D_FF];    // B lo

// ---------------- embedding gather ----------------
__global__ void embed_kernel(const int* __restrict__ tokens,
                             const float* __restrict__ emb,
                             float* __restrict__ x) {
    int idx = blockIdx.x * blockDim.x + threadIdx.x;
    int tok = idx >> 5;
    int j   = idx & 31;
    int t = tokens[tok];
    ((float4*)x)[idx] = ((const float4*)emb)[t * 32 + j];
}

// ---------------- LayerNorm fused with bf16 hi/lo split output ----------------
__global__ void ln_split_kernel(const float* __restrict__ x,
                                const float* __restrict__ w,
                                const float* __restrict__ b,
                                __nv_bfloat16* __restrict__ oh,
                                __nv_bfloat16* __restrict__ ol) {
    int row  = blockIdx.x * blockDim.y + threadIdx.y;
    int lane = threadIdx.x;
    const float4* xr = (const float4*)(x + (size_t)row * D_MODEL);
    float4 v = xr[lane];
    float s = v.x + v.y + v.z + v.w;
    #pragma unroll
    for (int o = 16; o; o >>= 1) s += __shfl_xor_sync(0xffffffffu, s, o);
    float mu = s * (1.0f / 128.0f);
    float d0 = v.x - mu, d1 = v.y - mu, d2 = v.z - mu, d3 = v.w - mu;
    float vs = d0*d0 + d1*d1 + d2*d2 + d3*d3;
    #pragma unroll
    for (int o = 16; o; o >>= 1) vs += __shfl_xor_sync(0xffffffffu, vs, o);
    float inv = rsqrtf(vs * (1.0f / 128.0f) + 1e-5f);
    float4 wv = ((const float4*)w)[lane];
    float4 bv = ((const float4*)b)[lane];
    float o0 = d0 * inv * wv.x + bv.x;
    float o1 = d1 * inv * wv.y + bv.y;
    float o2 = d2 * inv * wv.z + bv.z;
    float o3 = d3 * inv * wv.w + bv.w;
    size_t base = (size_t)row * D_MODEL + lane * 4;
    __nv_bfloat162 h0 = __floats2bfloat162_rn(o0, o1);
    __nv_bfloat162 h1 = __floats2bfloat162_rn(o2, o3);
    __nv_bfloat162 l0 = __floats2bfloat162_rn(o0 - __bfloat162float(h0.x),
                                              o1 - __bfloat162float(h0.y));
    __nv_bfloat162 l1 = __floats2bfloat162_rn(o2 - __bfloat162float(h1.x),
                                              o3 - __bfloat162float(h1.y));
    *(__nv_bfloat162*)(oh + base)     = h0;
    *(__nv_bfloat162*)(oh + base + 2) = h1;
    *(__nv_bfloat162*)(ol + base)     = l0;
    *(__nv_bfloat162*)(ol + base + 2) = l1;
}

// ---------------- split A (fp32 -> bf16 hi/lo), vectorized ----------------
__global__ void splitA_kernel(const float* __restrict__ in,
                              __nv_bfloat16* __restrict__ hi,
                              __nv_bfloat16* __restrict__ lo) {
    int i = blockIdx.x * blockDim.x + threadIdx.x;  // float4 index
    float4 v = ((const float4*)in)[i];
    __nv_bfloat162 h0 = __floats2bfloat162_rn(v.x, v.y);
    __nv_bfloat162 h1 = __floats2bfloat162_rn(v.z, v.w);
    __nv_bfloat162 l0 = __floats2bfloat162_rn(v.x - __bfloat162float(h0.x),
                                              v.y - __bfloat162float(h0.y));
    __nv_bfloat162 l1 = __floats2bfloat162_rn(v.z - __bfloat162float(h1.x),
                                              v.w - __bfloat162float(h1.y));
    size_t base = (size_t)i * 4;
    *(__nv_bfloat162*)(hi + base)     = h0;
    *(__nv_bfloat162*)(hi + base + 2) = h1;
    *(__nv_bfloat162*)(lo + base)     = l0;
    *(__nv_bfloat162*)(lo + base + 2) = l1;
}

// ---------------- split + transpose B: [K][N] fp32 -> [N][K] bf16 hi/lo ----
__global__ void splitB_kernel(const float* __restrict__ B,
                              __nv_bfloat16* __restrict__ bth,
                              __nv_bfloat16* __restrict__ btl,
                              int K, int N) {
    __shared__ float t[32][33];
    int k0 = blockIdx.y * 32, n0 = blockIdx.x * 32;
    int tx = threadIdx.x, ty = threadIdx.y;  // (32, 8)
    #pragma unroll
    for (int yy = 0; yy < 4; yy++)
        t[ty + 8 * yy][tx] = B[(size_t)(k0 + ty + 8 * yy) * N + n0 + tx];
    __syncthreads();
    #pragma unroll
    for (int yy = 0; yy < 4; yy++) {
        int n = n0 + ty + 8 * yy;
        float v = t[tx][ty + 8 * yy];
        __nv_bfloat16 h = __float2bfloat16(v);
        __nv_bfloat16 l = __float2bfloat16(v - __bfloat162float(h));
        bth[(size_t)n * K + k0 + tx] = h;
        btl[(size_t)n * K + k0 + tx] = l;
    }
}

// ================= 3-pass split-bf16 tensor-core GEMM =================
// C = act(A @ B + bias); A given as bf16 hi/lo [M][K]; B as bf16 hi/lo [N][K].
// Tile 128x128x32, 256 threads (8 warps: 4 m x 2 n). Drops lo*lo term.
#define AS_T 40                   // padded row stride (bf16 elems) -> conflict-free
#define TILE (128 * AS_T)         // bf16 elems per tile

__device__ __forceinline__ void cp_async16(void* smem, const void* gptr) {
    uint32_t s = (uint32_t)__cvta_generic_to_shared(smem);
    asm volatile("cp.async.cg.shared.global [%0], [%1], 16;\n" :: "r"(s), "l"(gptr));
}

#define MMA_BF16(d, a0,a1,a2,a3, b0,b1) \
    asm volatile("mma.sync.aligned.m16n8k16.row.col.f32.bf16.bf16.f32 " \
                 "{%0,%1,%2,%3},{%4,%5,%6,%7},{%8,%9},{%0,%1,%2,%3};\n" \
                 : "+f"(d[0]), "+f"(d[1]), "+f"(d[2]), "+f"(d[3]) \
                 : "r"(a0), "r"(a1), "r"(a2), "r"(a3), "r"(b0), "r"(b1))

__global__ __launch_bounds__(256)
void mma_bf16_kernel(const __nv_bfloat16* __restrict__ Ah,
                     const __nv_bfloat16* __restrict__ Al,
                     const __nv_bfloat16* __restrict__ Bh,   // [N][K]
                     const __nv_bfloat16* __restrict__ Bl,
                     const float* __restrict__ bias,
                     float* __restrict__ C,
                     int M, int N, int K, int act) {
    extern __shared__ __nv_bfloat16 sm[];
    int tid  = threadIdx.x;
    int lane = tid & 31;
    int wid  = tid >> 5;
    int warp_m = wid & 3;
    int warp_n = wid >> 2;
    int row0 = blockIdx.y * 128;
    int col0 = blockIdx.x * 128;
    int g = lane >> 2;            // group id
    int tq = lane & 3;            // thread in group

    float acc[2][8][4];
    #pragma unroll
    for (int i = 0; i < 2; i++)
        #pragma unroll
        for (int j = 0; j < 8; j++)
            #pragma unroll
            for (int k = 0; k < 4; k++) acc[i][j][k] = 0.0f;

    int nIter = K / 32;

    auto load_tiles = [&](int it, int stage) {
        int k0 = it * 32;
        __nv_bfloat16* s = sm + stage * 4 * TILE;
        #pragma unroll
        for (int j = 0; j < 2; j++) {
            int id = tid + j * 256;
            int r  = id >> 2;
            int cc = (id & 3) * 8;
            size_t ga = (size_t)(row0 + r) * K + k0 + cc;
            size_t gb = (size_t)(col0 + r) * K + k0 + cc;
            int so = r * AS_T + cc;
            cp_async16(&s[so],            &Ah[ga]);
            cp_async16(&s[TILE + so],     &Al[ga]);
            cp_async16(&s[2 * TILE + so], &Bh[gb]);
            cp_async16(&s[3 * TILE + so], &Bl[gb]);
        }
        asm volatile("cp.async.commit_group;\n");
    };

    load_tiles(0, 0);

    for (int it = 0; it < nIter; it++) {
        if (it + 1 < nIter) {
            load_tiles(it + 1, (it + 1) & 1);
            asm volatile("cp.async.wait_group 1;\n");
        } else {
            asm volatile("cp.async.wait_group 0;\n");
        }
        __syncthreads();

        const __nv_bfloat16* s  = sm + (it & 1) * 4 * TILE;
        const __nv_bfloat16* sa = s;
        const __nv_bfloat16* sl = s + TILE;
        const __nv_bfloat16* sb = s + 2 * TILE;
        const __nv_bfloat16* sc = s + 3 * TILE;

        #pragma unroll
        for (int kk = 0; kk < 2; kk++) {
            int cbase = kk * 16 + tq * 2;
            uint32_t ah[2][4], al[2][4];
            #pragma unroll
            for (int mi = 0; mi < 2; mi++) {
                int r = warp_m * 32 + mi * 16 + g;
                int o = r * AS_T + cbase;
                ah[mi][0] = *(const uint32_t*)(sa + o);
                ah[mi][1] = *(const uint32_t*)(sa + o + 8 * AS_T);
                ah[mi][2] = *(const uint32_t*)(sa + o + 8);
                ah[mi][3] = *(const uint32_t*)(sa + o + 8 * AS_T + 8);
                al[mi][0] = *(const uint32_t*)(sl + o);
                al[mi][1] = *(const uint32_t*)(sl + o + 8 * AS_T);
                al[mi][2] = *(const uint32_t*)(sl + o + 8);
                al[mi][3] = *(const uint32_t*)(sl + o + 8 * AS_T + 8);
            }
            #pragma unroll
            for (int ni = 0; ni < 8; ni++) {
                int n = warp_n * 64 + ni * 8 + g;
                int o = n * AS_T + cbase;
                uint32_t bh0 = *(const uint32_t*)(sb + o);
                uint32_t bh1 = *(const uint32_t*)(sb + o + 8);
                uint32_t bl0 = *(const uint32_t*)(sc + o);
                uint32_t bl1 = *(const uint32_t*)(sc + o + 8);
                #pragma unroll
                for (int mi = 0; mi < 2; mi++) {
                    MMA_BF16(acc[mi][ni], ah[mi][0], ah[mi][1], ah[mi][2], ah[mi][3], bl0, bl1);
                    MMA_BF16(acc[mi][ni], al[mi][0], al[mi][1], al[mi][2], al[mi][3], bh0, bh1);
                    MMA_BF16(acc[mi][ni], ah[mi][0], ah[mi][1], ah[mi][2], ah[mi][3], bh0, bh1);
                }
            }
        }
        __syncthreads();
    }

    // epilogue
    #pragma unroll
    for (int mi = 0; mi < 2; mi++) {
        int r0 = row0 + warp_m * 32 + mi * 16 + g;
        #pragma unroll
        for (int ni = 0; ni < 8; ni++) {
            int c0 = col0 + warp_n * 64 + ni * 8 + tq * 2;
            float b0 = 0.f, b1 = 0.f;
            if (bias) { b0 = bias[c0]; b1 = bias[c0 + 1]; }
            float v0 = acc[mi][ni][0] + b0;
            float v1 = acc[mi][ni][1] + b1;
            float v2 = acc[mi][ni][2] + b0;
            float v3 = acc[mi][ni][3] + b1;
            if (act == 1) {
                v0 = fmaxf(v0, 0.f); v1 = fmaxf(v1, 0.f);
                v2 = fmaxf(v2, 0.f); v3 = fmaxf(v3, 0.f);
            }
            *(float2*)&C[(size_t)r0 * N + c0]       = make_float2(v0, v1);
            *(float2*)&C[(size_t)(r0 + 8) * N + c0] = make_float2(v2, v3);
        }
    }
}
#define MMA_SMEM_B (2 * 4 * TILE * 2)   // bytes: 2 stages x 4 tiles x TILE bf16

// ---------------- small fp32 GEMM (kept for xproj, N=40) ----------------
#define GBM 64
#define GBN 64
#define GBK 16
__global__ void gemm_kernel(const float* __restrict__ A,
                            const float* __restrict__ B,
                            const float* __restrict__ bias,
                            float* __restrict__ C,
                            int M, int N, int K, int act) {
    __shared__ float As[GBK][GBM];
    __shared__ float Bs[GBK][GBN + 4];
    int tid = threadIdx.x;
    int tm = tid >> 4, tn = tid & 15;
    int row0 = blockIdx.y * GBM;
    int col0 = blockIdx.x * GBN;
    float acc[4][4] = {};
    for (int k0 = 0; k0 < K; k0 += GBK) {
        #pragma unroll
        for (int i = tid; i < GBM * GBK; i += 256) {
            int m = i >> 4, kk = i & 15;
            int gm = row0 + m, gk = k0 + kk;
            As[kk][m] = (gm < M && gk < K) ? A[(size_t)gm * K + gk] : 0.0f;
        }
        #pragma unroll
        for (int i = tid; i < GBK * GBN; i += 256) {
            int kk = i >> 6, n = i & 63;
            int gk = k0 + kk, gn = col0 + n;
            Bs[kk][n] = (gk < K && gn < N) ? B[(size_t)gk * N + gn] : 0.0f;
        }
        __syncthreads();
        #pragma unroll
        for (int kk = 0; kk < GBK; kk++) {
            float a[4], bb[4];
            #pragma unroll
            for (int i = 0; i < 4; i++) a[i] = As[kk][tm * 4 + i];
            #pragma unroll
            for (int j = 0; j < 4; j++) bb[j] = Bs[kk][tn * 4 + j];
            #pragma unroll
            for (int i = 0; i < 4; i++)
                #pragma unroll
                for (int j = 0; j < 4; j++)
                    acc[i][j] = fmaf(a[i], bb[j], acc[i][j]);
        }
        __syncthreads();
    }
    #pragma unroll
    for (int i = 0; i < 4; i++) {
        int gm = row0 + tm * 4 + i;
        if (gm >= M) continue;
        #pragma unroll
        for (int j = 0; j < 4; j++) {
            int gn = col0 + tn * 4 + j;
            if (gn >= N) continue;
            float v = acc[i][j];
            if (bias) v += bias[gn];
            if (act == 1) v = fmaxf(v, 0.0f);
            C[(size_t)gm * N + gn] = v;
        }
    }
}

// ---------------- depthwise causal conv (k=4) + SiLU ----------------
__global__ void conv_silu_kernel(const float* __restrict__ xz,
                                 const float* __restrict__ cw,
                                 const float* __restrict__ cb,
                                 float* __restrict__ u) {
    int idx = blockIdx.x * blockDim.x + threadIdx.x;
    int d   = idx & (D_INNER - 1);
    int tok = idx >> 8;
    int l   = tok & (LL - 1);
    float acc = cb[d];
    #pragma unroll
    for (int j = 0; j < 4; j++) {
        int tl = l - 3 + j;
        if (tl >= 0)
            acc = fmaf(cw[d * 4 + j], xz[(size_t)(tok - 3 + j) * (2*D_INNER) + d], acc);
    }
    u[idx] = acc / (1.0f + __expf(-acc));
}

// ---------------- dt = softplus(dt_r @ W_dt + b_dt) ----------------
__global__ void dt_kernel(const float* __restrict__ dbc,
                          const float* __restrict__ Wdt,
                          const float* __restrict__ bdt,
                          float* __restrict__ dt) {
    int idx = blockIdx.x * blockDim.x + threadIdx.x;
    int d   = idx & (D_INNER - 1);
    int tok = idx >> 8;
    const float* r = dbc + (size_t)tok * 40;
    float s = bdt[d];
    #pragma unroll
    for (int j = 0; j < 8; j++)
        s = fmaf(r[j], Wdt[j * D_INNER + d], s);
    dt[idx] = (s > 20.0f) ? s : log1pf(__expf(s));
}

// ---------------- selective scan (fused epilogue -> bf16 hi/lo y) -----------
#define SCHUNK 64
__global__ void scan_kernel(const float* __restrict__ dt,
                            const float* __restrict__ u,
                            const float* __restrict__ dbc,
                            const float* __restrict__ xz,
                            const float* __restrict__ A_log,
                            const float* __restrict__ Dskip,
                            __nv_bfloat16* __restrict__ yh,
                            __nv_bfloat16* __restrict__ yl) {
    __shared__ float sB [SCHUNK][16];
    __shared__ float sC [SCHUNK][16];
    __shared__ float sdt[SCHUNK][16];
    __shared__ float su [SCHUNK][16];
    __shared__ float sz [SCHUNK][16];
    __shared__ float sy [SCHUNK][16];
    int b   = blockIdx.x >> 4;
    int ch0 = (blockIdx.x & 15) * 16;
    int tid = threadIdx.x;
    int cl  = tid >> 4;
    int s   = tid & 15;
    int ch  = ch0 + cl;
    float A  = -__expf(A_log[ch * D_STATE + s]);
    float Ds = Dskip[ch];
    float h = 0.0f;
    size_t base_tok = (size_t)b * LL;
    for (int t0 = 0; t0 < LL; t0 += SCHUNK) {
        for (int i = tid; i < SCHUNK * 16; i += 256) {
            int st = i >> 4, j = i & 15;
            size_t tok = base_tok + t0 + st;
            sB [st][j] = dbc[tok * 40 + 8  + j];
            sC [st][j] = dbc[tok * 40 + 24 + j];
            sdt[st][j] = dt [tok * D_INNER + ch0 + j];
            su [st][j] = u  [tok * D_INNER + ch0 + j];
            sz [st][j] = xz [tok * (2*D_INNER) + D_INNER + ch0 + j];
        }
        __syncthreads();
        #pragma unroll 4
        for (int i = 0; i < SCHUNK; i++) {
            float dtv = sdt[i][cl];
            float uv  = su [i][cl];
            float dA  = __expf(dtv * A);
            h = fmaf(dA, h, dtv * uv * sB[i][s]);
            float p = h * sC[i][s];
            p += __shfl_xor_sync(0xffffffffu, p, 8);
            p += __shfl_xor_sync(0xffffffffu, p, 4);
            p += __shfl_xor_sync(0xffffffffu, p, 2);
            p += __shfl_xor_sync(0xffffffffu, p, 1);
            if (s == 0) {
                float zv = sz[i][cl];
                float yv = p + uv * Ds;
                yv *= zv / (1.0f + __expf(-zv));
                sy[i][cl] = yv;
            }
        }
        __syncthreads();
        for (int i = tid; i < SCHUNK * 16; i += 256) {
            int st = i >> 4, j = i & 15;
            float yv = sy[st][j];
            __nv_bfloat16 hh = __float2bfloat16(yv);
            __nv_bfloat16 lo = __float2bfloat16(yv - __bfloat162float(hh));
            size_t o = (base_tok + t0 + st) * D_INNER + ch0 + j;
            yh[o] = hh;
            yl[o] = lo;
        }
        __syncthreads();
    }
}

// ---------------- host launcher ----------------
extern "C" void kernel_launch(void* const* d_in, const int* in_sizes, int n_in,
                              void* d_out, int out_size) {
    const int*   tokens  = (const int*)  d_in[0];
    const float* emb     = (const float*)d_in[1];
    const float* ln_w    = (const float*)d_in[2];
    const float* ln_b    = (const float*)d_in[3];
    const float* W_in    = (const float*)d_in[4];
    const float* conv_w  = (const float*)d_in[5];
    const float* conv_b  = (const float*)d_in[6];
    const float* W_xproj = (const float*)d_in[7];
    const float* W_dt    = (const float*)d_in[8];
    const float* b_dt    = (const float*)d_in[9];
    const float* A_log   = (const float*)d_in[10];
    const float* D_skip  = (const float*)d_in[11];
    const float* W_out   = (const float*)d_in[12];
    const float* W1      = (const float*)d_in[13];
    const float* b1      = (const float*)d_in[14];
    const float* W2      = (const float*)d_in[15];
    const float* b2      = (const float*)d_in[16];
    float* out = (float*)d_out;

    float *x, *xz, *u, *dbc, *dt, *h1;
    __nv_bfloat16 *ah, *al, *bh, *bl;
    cudaGetSymbolAddress((void**)&x,   g_x);
    cudaGetSymbolAddress((void**)&xz,  g_xz);
    cudaGetSymbolAddress((void**)&u,   g_u);
    cudaGetSymbolAddress((void**)&dbc, g_db);
    cudaGetSymbolAddress((void**)&dt,  g_dt);
    cudaGetSymbolAddress((void**)&h1,  g_h1);
    cudaGetSymbolAddress((void**)&ah,  g_ah);
    cudaGetSymbolAddress((void**)&al,  g_al);
    cudaGetSymbolAddress((void**)&bh,  g_bh);
    cudaGetSymbolAddress((void**)&bl,  g_bl);

    cudaFuncSetAttribute(mma_bf16_kernel,
                         cudaFuncAttributeMaxDynamicSharedMemorySize, MMA_SMEM_B);

    embed_kernel<<<(NTOK * 32) / 256, 256>>>(tokens, emb, x);

    for (int l = 0; l < N_LAYERS; l++) {
        const float* lw  = ln_w    + l * D_MODEL;
        const float* lb  = ln_b    + l * D_MODEL;
        const float* wi  = W_in    + (size_t)l * D_MODEL * 2 * D_INNER;
        const float* cw  = conv_w  + (size_t)l * D_INNER * D_CONV;
        const float* cb  = conv_b  + (size_t)l * D_INNER;
        const float* wx  = W_xproj + (size_t)l * D_INNER * 40;
        const float* wd  = W_dt    + (size_t)l * DT_RANK * D_INNER;
        const float* bd  = b_dt    + (size_t)l * D_INNER;
        const float* al_ = A_log   + (size_t)l * D_INNER * D_STATE;
        const float* dsk = D_skip  + (size_t)l * D_INNER;
        const float* wo  = W_out   + (size_t)l * D_INNER * D_MODEL;

        // LN -> split bf16 A
        ln_split_kernel<<<NTOK / 8, dim3(32, 8)>>>(x, lw, lb, ah, al);
        // split W_in [128][512] -> [512][128]
        splitB_kernel<<<dim3(512 / 32, 128 / 32), dim3(32, 8)>>>(wi, bh, bl, 128, 512);
        // xz = ln @ W_in  [32768 x 512], K=128
        mma_bf16_kernel<<<dim3(512 / 128, NTOK / 128), 256, MMA_SMEM_B>>>(
            ah, al, bh, bl, nullptr, xz, NTOK, 512, 128, 0);
        conv_silu_kernel<<<NTOK * D_INNER / 256, 256>>>(xz, cw, cb, u);
        // dbc = u @ W_xproj  [32768 x 40], K=256  (fp32)
        gemm_kernel<<<dim3(1, NTOK / GBM), 256>>>(u, wx, nullptr, dbc,
                                                  NTOK, 40, 256, 0);
        dt_kernel<<<NTOK * D_INNER / 256, 256>>>(dbc, wd, bd, dt);
        // scan -> split bf16 y into ah/al
        scan_kernel<<<BB * 16, 256>>>(dt, u, dbc, xz, al_, dsk, ah, al);
        // split W_out [256][128] -> [128][256]
        splitB_kernel<<<dim3(128 / 32, 256 / 32), dim3(32, 8)>>>(wo, bh, bl, 256, 128);
        // x = y @ W_out  [32768 x 128], K=256
        mma_bf16_kernel<<<dim3(128 / 128, NTOK / 128), 256, MMA_SMEM_B>>>(
            ah, al, bh, bl, nullptr, x, NTOK, 128, 256, 0);
    }

    // head: h1 = relu(x @ W1 + b1)
    splitA_kernel<<<NTOK * D_MODEL / 4 / 256, 256>>>(x, ah, al);
    splitB_kernel<<<dim3(512 / 32, 128 / 32), dim3(32, 8)>>>(W1, bh, bl, 128, 512);
    mma_bf16_kernel<<<dim3(512 / 128, NTOK / 128), 256, MMA_SMEM_B>>>(
        ah, al, bh, bl, b1, h1, NTOK, D_FF, D_MODEL, 1);
    // out = h1 @ W2 + b2
    splitA_kernel<<<NTOK * D_FF / 4 / 256, 256>>>(h1, ah, al);
    splitB_kernel<<<dim3(VOCAB / 32, 512 / 32), dim3(32, 8)>>>(W2, bh, bl, 512, VOCAB);
    mma_bf16_kernel<<<dim3(VOCAB / 128, NTOK / 128), 256, MMA_SMEM_B>>>(
        ah, al, bh, bl, b2, out, NTOK, VOCAB, D_FF, 0);
}

// round 12
// speedup vs baseline: 3.9990x; 1.9717x over previous
#include <cuda_runtime.h>
#include <cuda_bf16.h>
#include <cstdint>

// Model constants
#define D_MODEL 128
#define VOCAB   4096
#define N_LAYERS 4
#define D_FF    512
#define D_INNER 256
#define D_STATE 16
#define D_CONV  4
#define DT_RANK 8
#define BB      8
#define LL      4096
#define NTOK    (BB*LL)   // 32768
#define NCHUNK  16
#define CLEN    256       // LL / NCHUNK
#define SCH     64

// ---------------- scratch (device globals: no allocations allowed) ----------
__device__ float g_x [NTOK * D_MODEL];
__device__ float g_xz[NTOK * 2*D_INNER];
__device__ float g_u [NTOK * D_INNER];
__device__ float g_db[NTOK * 40];
// bf16 split buffers
__device__ __nv_bfloat16 g_ah[NTOK * D_FF];     // activations hi
__device__ __nv_bfloat16 g_al[NTOK * D_FF];     // activations lo
__device__ __nv_bfloat16 g_xh[NTOK * D_MODEL];  // x split (head input)
__device__ __nv_bfloat16 g_xl[NTOK * D_MODEL];
__device__ __nv_bfloat16 g_bh[VOCAB * D_FF];    // weights hi, [N][K]
__device__ __nv_bfloat16 g_bl[VOCAB * D_FF];
// scan chunk state
__device__ float g_S [BB * D_INNER * NCHUNK * D_STATE];
__device__ float g_Hc[BB * D_INNER * NCHUNK * D_STATE];
__device__ float g_Dc[BB * D_INNER * NCHUNK];

// ---------------- embedding gather ----------------
__global__ void embed_kernel(const int* __restrict__ tokens,
                             const float* __restrict__ emb,
                             float* __restrict__ x) {
    int idx = blockIdx.x * blockDim.x + threadIdx.x;
    int tok = idx >> 5;
    int j   = idx & 31;
    int t = tokens[tok];
    ((float4*)x)[idx] = ((const float4*)emb)[t * 32 + j];
}

// ---------------- LayerNorm fused with bf16 hi/lo split output --------------
__global__ void ln_split_kernel(const float* __restrict__ x,
                                const float* __restrict__ w,
                                const float* __restrict__ b,
                                __nv_bfloat16* __restrict__ oh,
                                __nv_bfloat16* __restrict__ ol) {
    int row  = blockIdx.x * blockDim.y + threadIdx.y;
    int lane = threadIdx.x;
    const float4* xr = (const float4*)(x + (size_t)row * D_MODEL);
    float4 v = xr[lane];
    float s = v.x + v.y + v.z + v.w;
    #pragma unroll
    for (int o = 16; o; o >>= 1) s += __shfl_xor_sync(0xffffffffu, s, o);
    float mu = s * (1.0f / 128.0f);
    float d0 = v.x - mu, d1 = v.y - mu, d2 = v.z - mu, d3 = v.w - mu;
    float vs = d0*d0 + d1*d1 + d2*d2 + d3*d3;
    #pragma unroll
    for (int o = 16; o; o >>= 1) vs += __shfl_xor_sync(0xffffffffu, vs, o);
    float inv = rsqrtf(vs * (1.0f / 128.0f) + 1e-5f);
    float4 wv = ((const float4*)w)[lane];
    float4 bv = ((const float4*)b)[lane];
    float o0 = d0 * inv * wv.x + bv.x;
    float o1 = d1 * inv * wv.y + bv.y;
    float o2 = d2 * inv * wv.z + bv.z;
    float o3 = d3 * inv * wv.w + bv.w;
    size_t base = (size_t)row * D_MODEL + lane * 4;
    __nv_bfloat162 h0 = __floats2bfloat162_rn(o0, o1);
    __nv_bfloat162 h1 = __floats2bfloat162_rn(o2, o3);
    __nv_bfloat162 l0 = __floats2bfloat162_rn(o0 - __bfloat162float(h0.x),
                                              o1 - __bfloat162float(h0.y));
    __nv_bfloat162 l1 = __floats2bfloat162_rn(o2 - __bfloat162float(h1.x),
                                              o3 - __bfloat162float(h1.y));
    *(__nv_bfloat162*)(oh + base)     = h0;
    *(__nv_bfloat162*)(oh + base + 2) = h1;
    *(__nv_bfloat162*)(ol + base)     = l0;
    *(__nv_bfloat162*)(ol + base + 2) = l1;
}

// ---------------- split + transpose B: [K][N] fp32 -> [N][K] bf16 hi/lo ----
__global__ void splitB_kernel(const float* __restrict__ B,
                              __nv_bfloat16* __restrict__ bth,
                              __nv_bfloat16* __restrict__ btl,
                              int K, int N) {
    __shared__ float t[32][33];
    int k0 = blockIdx.y * 32, n0 = blockIdx.x * 32;
    int tx = threadIdx.x, ty = threadIdx.y;  // (32, 8)
    #pragma unroll
    for (int yy = 0; yy < 4; yy++)
        t[ty + 8 * yy][tx] = B[(size_t)(k0 + ty + 8 * yy) * N + n0 + tx];
    __syncthreads();
    #pragma unroll
    for (int yy = 0; yy < 4; yy++) {
        int n = n0 + ty + 8 * yy;
        float v = t[tx][ty + 8 * yy];
        __nv_bfloat16 h = __float2bfloat16(v);
        __nv_bfloat16 l = __float2bfloat16(v - __bfloat162float(h));
        bth[(size_t)n * K + k0 + tx] = h;
        btl[(size_t)n * K + k0 + tx] = l;
    }
}

// ================= 3-pass split-bf16 tensor-core GEMM (ldmatrix + swizzle) ==
// Tile 128x128x32; 256 thr (8 warps: 4m x 2n); 3-stage cp.async pipeline.
// SMEM tile layout: 64 physical rows of 128B; logical (r, c16):
//   pr = r>>1, pc = (r&1)*4 + c16, pc ^= (pr & 7)  -> conflict-free LDSM/cp.async.
__device__ __forceinline__ int sw_off(int r, int c16) {  // bf16-elem offset
    int pr = r >> 1;
    int pc = ((r & 1) << 2) | c16;
    return (pr << 6) + ((pc ^ (pr & 7)) << 3);
}
__device__ __forceinline__ void cp_async16(uint32_t dst, const void* src) {
    asm volatile("cp.async.cg.shared.global [%0], [%1], 16;\n" :: "r"(dst), "l"(src));
}
#define LDSM4(r0,r1,r2,r3,a) \
    asm volatile("ldmatrix.sync.aligned.m8n8.x4.shared.b16 {%0,%1,%2,%3}, [%4];\n" \
        : "=r"(r0), "=r"(r1), "=r"(r2), "=r"(r3) : "r"(a))
#define MMA_BF16(d, a0,a1,a2,a3, b0,b1) \
    asm volatile("mma.sync.aligned.m16n8k16.row.col.f32.bf16.bf16.f32 " \
                 "{%0,%1,%2,%3},{%4,%5,%6,%7},{%8,%9},{%0,%1,%2,%3};\n" \
                 : "+f"(d[0]), "+f"(d[1]), "+f"(d[2]), "+f"(d[3]) \
                 : "r"(a0), "r"(a1), "r"(a2), "r"(a3), "r"(b0), "r"(b1))

#define STAGE_BYTES 32768    // 4 tiles x 8KB
#define MMA_SMEM    (3 * STAGE_BYTES)

__global__ __launch_bounds__(256)
void mma_bf16_kernel(const __nv_bfloat16* __restrict__ Ah,
                     const __nv_bfloat16* __restrict__ Al,
                     const __nv_bfloat16* __restrict__ Bh,   // [N][K]
                     const __nv_bfloat16* __restrict__ Bl,
                     const float* __restrict__ bias,
                     float* __restrict__ C,                  // may be null
                     __nv_bfloat16* __restrict__ Oh,         // may be null
                     __nv_bfloat16* __restrict__ Ol,
                     int M, int N, int K, int act) {
    extern __shared__ __nv_bfloat16 smemb[];
    uint32_t smemBase = (uint32_t)__cvta_generic_to_shared(smemb);
    const int tid  = threadIdx.x;
    const int lane = tid & 31;
    const int wid  = tid >> 5;
    const int warp_m = wid & 3;
    const int warp_n = wid >> 2;
    const int row0 = blockIdx.y * 128;
    const int col0 = blockIdx.x * 128;

    float acc[2][8][4];
    #pragma unroll
    for (int i = 0; i < 2; i++)
        #pragma unroll
        for (int j = 0; j < 8; j++)
            #pragma unroll
            for (int k = 0; k < 4; k++) acc[i][j][k] = 0.0f;

    // cp.async per-thread chunk coords (2 chunks per tile)
    int r_[2], c_[2], soff_[2];
    #pragma unroll
    for (int j = 0; j < 2; j++) {
        int id = tid + j * 256;
        r_[j] = id >> 2;
        c_[j] = id & 3;
        soff_[j] = 2 * sw_off(r_[j], c_[j]);
    }

    // ldmatrix within-tile byte offsets
    int aoff[2], boff[4];
    #pragma unroll
    for (int mi = 0; mi < 2; mi++)
        aoff[mi] = 2 * sw_off(warp_m * 32 + mi * 16 + (lane & 15), lane >> 4);
    #pragma unroll
    for (int np = 0; np < 4; np++)
        boff[np] = 2 * sw_off(warp_n * 64 + np * 16 + ((lane & 16) >> 1) + (lane & 7),
                              (lane >> 3) & 1);

    const int nIter = K / 32;

    auto load_tiles = [&](int it) {
        uint32_t sb = smemBase + (it % 3) * STAGE_BYTES;
        int k0 = it * 32;
        #pragma unroll
        for (int j = 0; j < 2; j++) {
            size_t ga = (size_t)(row0 + r_[j]) * K + k0 + c_[j] * 8;
            size_t gb = (size_t)(col0 + r_[j]) * K + k0 + c_[j] * 8;
            cp_async16(sb + soff_[j],         Ah + ga);
            cp_async16(sb + 8192  + soff_[j], Al + ga);
            cp_async16(sb + 16384 + soff_[j], Bh + gb);
            cp_async16(sb + 24576 + soff_[j], Bl + gb);
        }
        asm volatile("cp.async.commit_group;\n");
    };

    load_tiles(0);
    load_tiles(1);

    for (int it = 0; it < nIter; it++) {
        if (it + 2 < nIter) load_tiles(it + 2);
        int rem = nIter - 1 - it;
        if (rem >= 2)      asm volatile("cp.async.wait_group 2;\n");
        else if (rem == 1) asm volatile("cp.async.wait_group 1;\n");
        else               asm volatile("cp.async.wait_group 0;\n");
        __syncthreads();

        uint32_t sb = smemBase + (it % 3) * STAGE_BYTES;
        #pragma unroll
        for (int kk = 0; kk < 2; kk++) {
            const int kx = kk << 5;   // 32-byte XOR per 16-k step
            uint32_t ah[2][4], al[2][4];
            #pragma unroll
            for (int mi = 0; mi < 2; mi++) {
                LDSM4(ah[mi][0], ah[mi][1], ah[mi][2], ah[mi][3],
                      sb + (aoff[mi] ^ kx));
                LDSM4(al[mi][0], al[mi][1], al[mi][2], al[mi][3],
                      sb + 8192 + (aoff[mi] ^ kx));
            }
            #pragma unroll
            for (int np = 0; np < 4; np++) {
                uint32_t bh[4], bl[4];
                LDSM4(bh[0], bh[1], bh[2], bh[3], sb + 16384 + (boff[np] ^ kx));
                LDSM4(bl[0], bl[1], bl[2], bl[3], sb + 24576 + (boff[np] ^ kx));
                #pragma unroll
                for (int mi = 0; mi < 2; mi++) {
                    MMA_BF16(acc[mi][np*2],   ah[mi][0], ah[mi][1], ah[mi][2], ah[mi][3], bl[0], bl[1]);
                    MMA_BF16(acc[mi][np*2],   al[mi][0], al[mi][1], al[mi][2], al[mi][3], bh[0], bh[1]);
                    MMA_BF16(acc[mi][np*2],   ah[mi][0], ah[mi][1], ah[mi][2], ah[mi][3], bh[0], bh[1]);
                    MMA_BF16(acc[mi][np*2+1], ah[mi][0], ah[mi][1], ah[mi][2], ah[mi][3], bl[2], bl[3]);
                    MMA_BF16(acc[mi][np*2+1], al[mi][0], al[mi][1], al[mi][2], al[mi][3], bh[2], bh[3]);
                    MMA_BF16(acc[mi][np*2+1], ah[mi][0], ah[mi][1], ah[mi][2], ah[mi][3], bh[2], bh[3]);
                }
            }
        }
        __syncthreads();
    }

    // epilogue
    const int g = lane >> 2, tq = lane & 3;
    #pragma unroll
    for (int mi = 0; mi < 2; mi++) {
        int r0 = row0 + warp_m * 32 + mi * 16 + g;
        #pragma unroll
        for (int ni = 0; ni < 8; ni++) {
            int c0 = col0 + warp_n * 64 + ni * 8 + tq * 2;
            float b0 = 0.f, b1 = 0.f;
            if (bias) { b0 = bias[c0]; b1 = bias[c0 + 1]; }
            float v0 = acc[mi][ni][0] + b0;
            float v1 = acc[mi][ni][1] + b1;
            float v2 = acc[mi][ni][2] + b0;
            float v3 = acc[mi][ni][3] + b1;
            if (act == 1) {
                v0 = fmaxf(v0, 0.f); v1 = fmaxf(v1, 0.f);
                v2 = fmaxf(v2, 0.f); v3 = fmaxf(v3, 0.f);
            }
            size_t o0 = (size_t)r0 * N + c0;
            size_t o1 = (size_t)(r0 + 8) * N + c0;
            if (C) {
                *(float2*)&C[o0] = make_float2(v0, v1);
                *(float2*)&C[o1] = make_float2(v2, v3);
            }
            if (Oh) {
                __nv_bfloat162 h0 = __floats2bfloat162_rn(v0, v1);
                __nv_bfloat162 h1 = __floats2bfloat162_rn(v2, v3);
                __nv_bfloat162 l0 = __floats2bfloat162_rn(v0 - __bfloat162float(h0.x),
                                                          v1 - __bfloat162float(h0.y));
                __nv_bfloat162 l1 = __floats2bfloat162_rn(v2 - __bfloat162float(h1.x),
                                                          v3 - __bfloat162float(h1.y));
                *(__nv_bfloat162*)(Oh + o0) = h0;
                *(__nv_bfloat162*)(Oh + o1) = h1;
                *(__nv_bfloat162*)(Ol + o0) = l0;
                *(__nv_bfloat162*)(Ol + o1) = l1;
            }
        }
    }
}

// ---------------- small fp32 GEMM (xproj, N=40) ----------------
#define GBM 64
#define GBN 64
#define GBK 16
__global__ void gemm_kernel(const float* __restrict__ A,
                            const float* __restrict__ B,
                            float* __restrict__ C,
                            int M, int N, int K) {
    __shared__ float As[GBK][GBM];
    __shared__ float Bs[GBK][GBN + 4];
    int tid = threadIdx.x;
    int tm = tid >> 4, tn = tid & 15;
    int row0 = blockIdx.y * GBM;
    int col0 = blockIdx.x * GBN;
    float acc[4][4] = {};
    for (int k0 = 0; k0 < K; k0 += GBK) {
        #pragma unroll
        for (int i = tid; i < GBM * GBK; i += 256) {
            int m = i >> 4, kk = i & 15;
            As[kk][m] = A[(size_t)(row0 + m) * K + k0 + kk];
        }
        #pragma unroll
        for (int i = tid; i < GBK * GBN; i += 256) {
            int kk = i >> 6, n = i & 63;
            int gn = col0 + n;
            Bs[kk][n] = (gn < N) ? B[(size_t)(k0 + kk) * N + gn] : 0.0f;
        }
        __syncthreads();
        #pragma unroll
        for (int kk = 0; kk < GBK; kk++) {
            float a[4], bb[4];
            #pragma unroll
            for (int i = 0; i < 4; i++) a[i] = As[kk][tm * 4 + i];
            #pragma unroll
            for (int j = 0; j < 4; j++) bb[j] = Bs[kk][tn * 4 + j];
            #pragma unroll
            for (int i = 0; i < 4; i++)
                #pragma unroll
                for (int j = 0; j < 4; j++)
                    acc[i][j] = fmaf(a[i], bb[j], acc[i][j]);
        }
        __syncthreads();
    }
    #pragma unroll
    for (int i = 0; i < 4; i++) {
        int gm = row0 + tm * 4 + i;
        #pragma unroll
        for (int j = 0; j < 4; j++) {
            int gn = col0 + tn * 4 + j;
            if (gn < N) C[(size_t)gm * N + gn] = acc[i][j];
        }
    }
}

// ---------------- depthwise causal conv (k=4) + SiLU ----------------
__global__ void conv_silu_kernel(const float* __restrict__ xz,
                                 const float* __restrict__ cw,
                                 const float* __restrict__ cb,
                                 float* __restrict__ u) {
    int idx = blockIdx.x * blockDim.x + threadIdx.x;
    int d   = idx & (D_INNER - 1);
    int tok = idx >> 8;
    int l   = tok & (LL - 1);
    float acc = cb[d];
    #pragma unroll
    for (int j = 0; j < 4; j++) {
        int tl = l - 3 + j;
        if (tl >= 0)
            acc = fmaf(cw[d * 4 + j], xz[(size_t)(tok - 3 + j) * (2*D_INNER) + d], acc);
    }
    u[idx] = acc / (1.0f + __expf(-acc));
}

// ================= chunk-parallel selective scan =================
// pass1: per (b, chgroup, chunk): local scan from h=0, output chunk-end state S
//        and sum(dt) per channel.  dt computed inline from dbc + W_dt.
__global__ void scan1_kernel(const float* __restrict__ u,
                             const float* __restrict__ dbc,
                             const float* __restrict__ Wdt,
                             const float* __restrict__ bdt,
                             const float* __restrict__ A_log,
                             float* __restrict__ Sbuf,
                             float* __restrict__ Dbuf) {
    __shared__ float sR [SCH][8];
    __shared__ float sB [SCH][16];
    __shared__ float su [SCH][16];
    __shared__ float sdt[SCH][16];
    __shared__ float swt[8][16];
    __shared__ float sbd[16];
    int chunk = blockIdx.x, chg = blockIdx.y, b = blockIdx.z;
    int ch0 = chg * 16;
    int tid = threadIdx.x;
    int cl  = tid >> 4;
    int s   = tid & 15;
    int ch  = ch0 + cl;
    if (tid < 128) swt[tid >> 4][tid & 15] = Wdt[(tid >> 4) * D_INNER + ch0 + (tid & 15)];
    if (tid < 16)  sbd[tid] = bdt[ch0 + tid];
    float A = -__expf(A_log[ch * D_STATE + s]);
    float h = 0.0f, sum = 0.0f;
    size_t tokbase = (size_t)b * LL + (size_t)chunk * CLEN;
    __syncthreads();
    for (int t0 = 0; t0 < CLEN; t0 += SCH) {
        for (int i = tid; i < SCH * 8; i += 256) {
            int st = i >> 3, j = i & 7;
            sR[st][j] = dbc[(tokbase + t0 + st) * 40 + j];
        }
        for (int i = tid; i < SCH * 16; i += 256) {
            int st = i >> 4, j = i & 15;
            sB[st][j] = dbc[(tokbase + t0 + st) * 40 + 8 + j];
            su[st][j] = u  [(tokbase + t0 + st) * D_INNER + ch0 + j];
        }
        __syncthreads();
        for (int i = tid; i < SCH * 16; i += 256) {
            int st = i >> 4, j = i & 15;
            float a = sbd[j];
            #pragma unroll
            for (int jj = 0; jj < 8; jj++) a = fmaf(sR[st][jj], swt[jj][j], a);
            sdt[st][j] = (a > 20.0f) ? a : log1pf(__expf(a));
        }
        __syncthreads();
        #pragma unroll 4
        for (int i = 0; i < SCH; i++) {
            float dtv = sdt[i][cl];
            h = fmaf(__expf(dtv * A), h, dtv * su[i][cl] * sB[i][s]);
            sum += dtv;
        }
        __syncthreads();
    }
    size_t o = (((size_t)b * D_INNER + ch) * NCHUNK + chunk) * 16 + s;
    Sbuf[o] = h;
    if (s == 0) Dbuf[((size_t)b * D_INNER + ch) * NCHUNK + chunk] = sum;
}

// combine: sequential over 16 chunks per (b, ch, s)
__global__ void scanc_kernel(const float* __restrict__ A_log,
                             const float* __restrict__ Sbuf,
                             const float* __restrict__ Dbuf,
                             float* __restrict__ Hbuf) {
    int idx = blockIdx.x * 256 + threadIdx.x;   // b*4096 + ch*16 + s
    int s  = idx & 15;
    int ch = (idx >> 4) & 255;
    int b  = idx >> 12;
    float A = -__expf(A_log[ch * D_STATE + s]);
    float h = 0.0f;
    size_t base = ((size_t)b * D_INNER + ch) * NCHUNK;
    #pragma unroll
    for (int c = 0; c < NCHUNK; c++) {
        Hbuf[(base + c) * 16 + s] = h;
        h = fmaf(__expf(A * Dbuf[base + c]), h, Sbuf[(base + c) * 16 + s]);
    }
}

// pass2: full scan per chunk from Hbuf init; fused +u*D, *silu(z), bf16 split y
__global__ void scan2_kernel(const float* __restrict__ u,
                             const float* __restrict__ dbc,
                             const float* __restrict__ xz,
                             const float* __restrict__ Wdt,
                             const float* __restrict__ bdt,
                             const float* __restrict__ A_log,
                             const float* __restrict__ Dskip,
                             const float* __restrict__ Hbuf,
                             __nv_bfloat16* __restrict__ yh,
                             __nv_bfloat16* __restrict__ yl) {
    __shared__ float sR [SCH][8];
    __shared__ float sB [SCH][16];
    __shared__ float sC [SCH][16];
    __shared__ float su [SCH][16];
    __shared__ float sz [SCH][16];
    __shared__ float sdt[SCH][16];
    __shared__ float sy [SCH][16];
    __shared__ float swt[8][16];
    __shared__ float sbd[16];
    int chunk = blockIdx.x, chg = blockIdx.y, b = blockIdx.z;
    int ch0 = chg * 16;
    int tid = threadIdx.x;
    int cl  = tid >> 4;
    int s   = tid & 15;
    int ch  = ch0 + cl;
    if (tid < 128) swt[tid >> 4][tid & 15] = Wdt[(tid >> 4) * D_INNER + ch0 + (tid & 15)];
    if (tid < 16)  sbd[tid] = bdt[ch0 + tid];
    float A  = -__expf(A_log[ch * D_STATE + s]);
    float Ds = Dskip[ch];
    float h  = Hbuf[(((size_t)b * D_INNER + ch) * NCHUNK + chunk) * 16 + s];
    size_t tokbase = (size_t)b * LL + (size_t)chunk * CLEN;
    __syncthreads();
    for (int t0 = 0; t0 < CLEN; t0 += SCH) {
        for (int i = tid; i < SCH * 8; i += 256) {
            int st = i >> 3, j = i & 7;
            sR[st][j] = dbc[(tokbase + t0 + st) * 40 + j];
        }
        for (int i = tid; i < SCH * 16; i += 256) {
            int st = i >> 4, j = i & 15;
            size_t tok = tokbase + t0 + st;
            sB[st][j] = dbc[tok * 40 + 8  + j];
            sC[st][j] = dbc[tok * 40 + 24 + j];
            su[st][j] = u  [tok * D_INNER + ch0 + j];
            sz[st][j] = xz [tok * (2*D_INNER) + D_INNER + ch0 + j];
        }
        __syncthreads();
        for (int i = tid; i < SCH * 16; i += 256) {
            int st = i >> 4, j = i & 15;
            float a = sbd[j];
            #pragma unroll
            for (int jj = 0; jj < 8; jj++) a = fmaf(sR[st][jj], swt[jj][j], a);
            sdt[st][j] = (a > 20.0f) ? a : log1pf(__expf(a));
        }
        __syncthreads();
        #pragma unroll 4
        for (int i = 0; i < SCH; i++) {
            float dtv = sdt[i][cl];
            float uv  = su [i][cl];
            h = fmaf(__expf(dtv * A), h, dtv * uv * sB[i][s]);
            float p = h * sC[i][s];
            p += __shfl_xor_sync(0xffffffffu, p, 8);
            p += __shfl_xor_sync(0xffffffffu, p, 4);
            p += __shfl_xor_sync(0xffffffffu, p, 2);
            p += __shfl_xor_sync(0xffffffffu, p, 1);
            if (s == 0) {
                float zv = sz[i][cl];
                float yv = p + uv * Ds;
                yv *= zv / (1.0f + __expf(-zv));
                sy[i][cl] = yv;
            }
        }
        __syncthreads();
        for (int i = tid; i < SCH * 16; i += 256) {
            int st = i >> 4, j = i & 15;
            float yv = sy[st][j];
            __nv_bfloat16 hh = __float2bfloat16(yv);
            __nv_bfloat16 lo = __float2bfloat16(yv - __bfloat162float(hh));
            size_t o = (tokbase + t0 + st) * D_INNER + ch0 + j;
            yh[o] = hh;
            yl[o] = lo;
        }
        __syncthreads();
    }
}

// ---------------- host launcher ----------------
extern "C" void kernel_launch(void* const* d_in, const int* in_sizes, int n_in,
                              void* d_out, int out_size) {
    const int*   tokens  = (const int*)  d_in[0];
    const float* emb     = (const float*)d_in[1];
    const float* ln_w    = (const float*)d_in[2];
    const float* ln_b    = (const float*)d_in[3];
    const float* W_in    = (const float*)d_in[4];
    const float* conv_w  = (const float*)d_in[5];
    const float* conv_b  = (const float*)d_in[6];
    const float* W_xproj = (const float*)d_in[7];
    const float* W_dt    = (const float*)d_in[8];
    const float* b_dt    = (const float*)d_in[9];
    const float* A_log   = (const float*)d_in[10];
    const float* D_skip  = (const float*)d_in[11];
    const float* W_out   = (const float*)d_in[12];
    const float* W1      = (const float*)d_in[13];
    const float* b1      = (const float*)d_in[14];
    const float* W2      = (const float*)d_in[15];
    const float* b2      = (const float*)d_in[16];
    float* out = (float*)d_out;

    float *x, *xz, *u, *dbc, *S, *Hc, *Dc;
    __nv_bfloat16 *ah, *al, *xh, *xl, *bh, *bl;
    cudaGetSymbolAddress((void**)&x,   g_x);
    cudaGetSymbolAddress((void**)&xz,  g_xz);
    cudaGetSymbolAddress((void**)&u,   g_u);
    cudaGetSymbolAddress((void**)&dbc, g_db);
    cudaGetSymbolAddress((void**)&S,   g_S);
    cudaGetSymbolAddress((void**)&Hc,  g_Hc);
    cudaGetSymbolAddress((void**)&Dc,  g_Dc);
    cudaGetSymbolAddress((void**)&ah,  g_ah);
    cudaGetSymbolAddress((void**)&al,  g_al);
    cudaGetSymbolAddress((void**)&xh,  g_xh);
    cudaGetSymbolAddress((void**)&xl,  g_xl);
    cudaGetSymbolAddress((void**)&bh,  g_bh);
    cudaGetSymbolAddress((void**)&bl,  g_bl);

    cudaFuncSetAttribute(mma_bf16_kernel,
                         cudaFuncAttributeMaxDynamicSharedMemorySize, MMA_SMEM);

    embed_kernel<<<(NTOK * 32) / 256, 256>>>(tokens, emb, x);

    for (int l = 0; l < N_LAYERS; l++) {
        const float* lw  = ln_w    + l * D_MODEL;
        const float* lb  = ln_b    + l * D_MODEL;
        const float* wi  = W_in    + (size_t)l * D_MODEL * 2 * D_INNER;
        const float* cw  = conv_w  + (size_t)l * D_INNER * D_CONV;
        const float* cb  = conv_b  + (size_t)l * D_INNER;
        const float* wx  = W_xproj + (size_t)l * D_INNER * 40;
        const float* wd  = W_dt    + (size_t)l * DT_RANK * D_INNER;
        const float* bd  = b_dt    + (size_t)l * D_INNER;
        const float* alog= A_log   + (size_t)l * D_INNER * D_STATE;
        const float* dsk = D_skip  + (size_t)l * D_INNER;
        const float* wo  = W_out   + (size_t)l * D_INNER * D_MODEL;

        ln_split_kernel<<<NTOK / 8, dim3(32, 8)>>>(x, lw, lb, ah, al);
        splitB_kernel<<<dim3(512 / 32, 128 / 32), dim3(32, 8)>>>(wi, bh, bl, 128, 512);
        // xz = ln @ W_in  [32768 x 512], K=128
        mma_bf16_kernel<<<dim3(4, NTOK / 128), 256, MMA_SMEM>>>(
            ah, al, bh, bl, nullptr, xz, nullptr, nullptr, NTOK, 512, 128, 0);
        conv_silu_kernel<<<NTOK * D_INNER / 256, 256>>>(xz, cw, cb, u);
        // dbc = u @ W_xproj  [32768 x 40], K=256  (fp32)
        gemm_kernel<<<dim3(1, NTOK / GBM), 256>>>(u, wx, dbc, NTOK, 40, 256);
        // chunk-parallel scan (dt fused)
        scan1_kernel<<<dim3(NCHUNK, 16, BB), 256>>>(u, dbc, wd, bd, alog, S, Dc);
        scanc_kernel<<<BB * 4096 / 256, 256>>>(alog, S, Dc, Hc);
        scan2_kernel<<<dim3(NCHUNK, 16, BB), 256>>>(u, dbc, xz, wd, bd, alog,
                                                    dsk, Hc, ah, al);
        splitB_kernel<<<dim3(128 / 32, 256 / 32), dim3(32, 8)>>>(wo, bh, bl, 256, 128);
        // x = y @ W_out  [32768 x 128], K=256 ; also emit split x for head
        mma_bf16_kernel<<<dim3(1, NTOK / 128), 256, MMA_SMEM>>>(
            ah, al, bh, bl, nullptr, x, xh, xl, NTOK, 128, 256, 0);
    }

    // head: h1 = relu(x @ W1 + b1)  -> split only (no fp32 h1 needed)
    splitB_kernel<<<dim3(512 / 32, 128 / 32), dim3(32, 8)>>>(W1, bh, bl, 128, 512);
    mma_bf16_kernel<<<dim3(4, NTOK / 128), 256, MMA_SMEM>>>(
        xh, xl, bh, bl, b1, nullptr, ah, al, NTOK, D_FF, D_MODEL, 1);
    // out = h1 @ W2 + b2
    splitB_kernel<<<dim3(VOCAB / 32, 512 / 32), dim3(32, 8)>>>(W2, bh, bl, 512, VOCAB);
    mma_bf16_kernel<<<dim3(VOCAB / 128, NTOK / 128), 256, MMA_SMEM>>>(
        ah, al, bh, bl, b2, out, nullptr, nullptr, NTOK, VOCAB, D_FF, 0);
}

// round 14
// speedup vs baseline: 4.4895x; 1.1227x over previous
#include <cuda_runtime.h>
#include <cuda_bf16.h>
#include <cstdint>

// Model constants
#define D_MODEL 128
#define VOCAB   4096
#define N_LAYERS 4
#define D_FF    512
#define D_INNER 256
#define D_STATE 16
#define D_CONV  4
#define DT_RANK 8
#define BB      8
#define LL      4096
#define NTOK    (BB*LL)   // 32768
#define NCHUNK  16
#define CLEN    256
#define SCH     64

// ---------------- scratch (device globals: no allocations allowed) ----------
__device__ float g_x [NTOK * D_MODEL];
__device__ float g_xz[NTOK * 2*D_INNER];
__device__ float g_u [NTOK * D_INNER];
__device__ float g_db[NTOK * 40];
__device__ __nv_bfloat16 g_uh[NTOK * D_INNER];
__device__ __nv_bfloat16 g_ul[NTOK * D_INNER];
__device__ __nv_bfloat16 g_ah[NTOK * D_FF];
__device__ __nv_bfloat16 g_al[NTOK * D_FF];
__device__ __nv_bfloat16 g_xh[NTOK * D_MODEL];
__device__ __nv_bfloat16 g_xl[NTOK * D_MODEL];
__device__ __nv_bfloat16 g_bh[VOCAB * D_FF];
__device__ __nv_bfloat16 g_bl[VOCAB * D_FF];
__device__ float g_S [BB * D_INNER * NCHUNK * D_STATE];
__device__ float g_Hc[BB * D_INNER * NCHUNK * D_STATE];
__device__ float g_Dc[BB * D_INNER * NCHUNK];

// ---------------- embedding gather ----------------
__global__ void embed_kernel(const int* __restrict__ tokens,
                             const float* __restrict__ emb,
                             float* __restrict__ x) {
    int idx = blockIdx.x * blockDim.x + threadIdx.x;
    int tok = idx >> 5;
    int j   = idx & 31;
    int t = tokens[tok];
    ((float4*)x)[idx] = ((const float4*)emb)[t * 32 + j];
}

// ---------------- LayerNorm fused with bf16 hi/lo split output --------------
__global__ void ln_split_kernel(const float* __restrict__ x,
                                const float* __restrict__ w,
                                const float* __restrict__ b,
                                __nv_bfloat16* __restrict__ oh,
                                __nv_bfloat16* __restrict__ ol) {
    int row  = blockIdx.x * blockDim.y + threadIdx.y;
    int lane = threadIdx.x;
    const float4* xr = (const float4*)(x + (size_t)row * D_MODEL);
    float4 v = xr[lane];
    float s = v.x + v.y + v.z + v.w;
    #pragma unroll
    for (int o = 16; o; o >>= 1) s += __shfl_xor_sync(0xffffffffu, s, o);
    float mu = s * (1.0f / 128.0f);
    float d0 = v.x - mu, d1 = v.y - mu, d2 = v.z - mu, d3 = v.w - mu;
    float vs = d0*d0 + d1*d1 + d2*d2 + d3*d3;
    #pragma unroll
    for (int o = 16; o; o >>= 1) vs += __shfl_xor_sync(0xffffffffu, vs, o);
    float inv = rsqrtf(vs * (1.0f / 128.0f) + 1e-5f);
    float4 wv = ((const float4*)w)[lane];
    float4 bv = ((const float4*)b)[lane];
    float o0 = d0 * inv * wv.x + bv.x;
    float o1 = d1 * inv * wv.y + bv.y;
    float o2 = d2 * inv * wv.z + bv.z;
    float o3 = d3 * inv * wv.w + bv.w;
    size_t base = (size_t)row * D_MODEL + lane * 4;
    __nv_bfloat162 h0 = __floats2bfloat162_rn(o0, o1);
    __nv_bfloat162 h1 = __floats2bfloat162_rn(o2, o3);
    __nv_bfloat162 l0 = __floats2bfloat162_rn(o0 - __bfloat162float(h0.x),
                                              o1 - __bfloat162float(h0.y));
    __nv_bfloat162 l1 = __floats2bfloat162_rn(o2 - __bfloat162float(h1.x),
                                              o3 - __bfloat162float(h1.y));
    *(__nv_bfloat162*)(oh + base)     = h0;
    *(__nv_bfloat162*)(oh + base + 2) = h1;
    *(__nv_bfloat162*)(ol + base)     = l0;
    *(__nv_bfloat162*)(ol + base + 2) = l1;
}

// ---------------- split + transpose B (zero-padded to grid width) -----------
__global__ void splitB_kernel(const float* __restrict__ B,
                              __nv_bfloat16* __restrict__ bth,
                              __nv_bfloat16* __restrict__ btl,
                              int K, int Nsrc) {
    __shared__ float t[32][33];
    int k0 = blockIdx.y * 32, n0 = blockIdx.x * 32;
    int tx = threadIdx.x, ty = threadIdx.y;  // (32, 8)
    #pragma unroll
    for (int yy = 0; yy < 4; yy++) {
        int n = n0 + tx;
        t[ty + 8 * yy][tx] = (n < Nsrc)
            ? B[(size_t)(k0 + ty + 8 * yy) * Nsrc + n] : 0.0f;
    }
    __syncthreads();
    #pragma unroll
    for (int yy = 0; yy < 4; yy++) {
        int n = n0 + ty + 8 * yy;
        float v = t[tx][ty + 8 * yy];
        __nv_bfloat16 h = __float2bfloat16(v);
        __nv_bfloat16 l = __float2bfloat16(v - __bfloat162float(h));
        bth[(size_t)n * K + k0 + tx] = h;
        btl[(size_t)n * K + k0 + tx] = l;
    }
}

// ================= 3-pass split-bf16 tensor-core GEMM (ldmatrix + swizzle) ==
// Tile 128x128x32; 256 thr (8 warps: 4m x 2n); 3-stage cp.async pipeline,
// ONE __syncthreads per mainloop iteration (loads issued post-barrier).
__device__ __forceinline__ int sw_off(int r, int c16) {  // bf16-elem offset
    int pr = r >> 1;
    int pc = ((r & 1) << 2) | c16;
    return (pr << 6) + ((pc ^ (pr & 7)) << 3);
}
__device__ __forceinline__ void cp_async16(uint32_t dst, const void* src) {
    asm volatile("cp.async.cg.shared.global [%0], [%1], 16;\n" :: "r"(dst), "l"(src));
}
#define LDSM4(r0,r1,r2,r3,a) \
    asm volatile("ldmatrix.sync.aligned.m8n8.x4.shared.b16 {%0,%1,%2,%3}, [%4];\n" \
        : "=r"(r0), "=r"(r1), "=r"(r2), "=r"(r3) : "r"(a))
#define MMA_BF16(d, a0,a1,a2,a3, b0,b1) \
    asm volatile("mma.sync.aligned.m16n8k16.row.col.f32.bf16.bf16.f32 " \
                 "{%0,%1,%2,%3},{%4,%5,%6,%7},{%8,%9},{%0,%1,%2,%3};\n" \
                 : "+f"(d[0]), "+f"(d[1]), "+f"(d[2]), "+f"(d[3]) \
                 : "r"(a0), "r"(a1), "r"(a2), "r"(a3), "r"(b0), "r"(b1))

#define STAGE_BYTES 32768    // 4 tiles x 8KB
#define MMA_SMEM    (3 * STAGE_BYTES)

__global__ __launch_bounds__(256)
void mma_bf16_kernel(const __nv_bfloat16* __restrict__ Ah,
                     const __nv_bfloat16* __restrict__ Al,
                     const __nv_bfloat16* __restrict__ Bh,   // [Npad][K]
                     const __nv_bfloat16* __restrict__ Bl,
                     const float* __restrict__ bias,
                     float* __restrict__ C,                  // may be null
                     __nv_bfloat16* __restrict__ Oh,         // may be null
                     __nv_bfloat16* __restrict__ Ol,
                     int M, int Nld, int Nout, int K, int act) {
    extern __shared__ __nv_bfloat16 smemb[];
    uint32_t smemBase = (uint32_t)__cvta_generic_to_shared(smemb);
    const int tid  = threadIdx.x;
    const int lane = tid & 31;
    const int wid  = tid >> 5;
    const int warp_m = wid & 3;
    const int warp_n = wid >> 2;
    const int row0 = blockIdx.y * 128;
    const int col0 = blockIdx.x * 128;

    float acc[2][8][4];
    #pragma unroll
    for (int i = 0; i < 2; i++)
        #pragma unroll
        for (int j = 0; j < 8; j++)
            #pragma unroll
            for (int k = 0; k < 4; k++) acc[i][j][k] = 0.0f;

    // cp.async per-thread chunk coords (2 chunks per tile)
    int r_[2], c_[2], soff_[2];
    #pragma unroll
    for (int j = 0; j < 2; j++) {
        int id = tid + j * 256;
        r_[j] = id >> 2;
        c_[j] = id & 3;
        soff_[j] = 2 * sw_off(r_[j], c_[j]);
    }

    // ldmatrix within-tile byte offsets
    int aoff[2], boff[4];
    #pragma unroll
    for (int mi = 0; mi < 2; mi++)
        aoff[mi] = 2 * sw_off(warp_m * 32 + mi * 16 + (lane & 15), lane >> 4);
    #pragma unroll
    for (int np = 0; np < 4; np++)
        boff[np] = 2 * sw_off(warp_n * 64 + np * 16 + ((lane & 16) >> 1) + (lane & 7),
                              (lane >> 3) & 1);

    const int nIter = K / 32;

    auto load_tiles = [&](int it) {
        uint32_t sb = smemBase + (it % 3) * STAGE_BYTES;
        int k0 = it * 32;
        #pragma unroll
        for (int j = 0; j < 2; j++) {
            size_t ga = (size_t)(row0 + r_[j]) * K + k0 + c_[j] * 8;
            size_t gb = (size_t)(col0 + r_[j]) * K + k0 + c_[j] * 8;
            cp_async16(sb + soff_[j],         Ah + ga);
            cp_async16(sb + 8192  + soff_[j], Al + ga);
            cp_async16(sb + 16384 + soff_[j], Bh + gb);
            cp_async16(sb + 24576 + soff_[j], Bl + gb);
        }
        asm volatile("cp.async.commit_group;\n");
    };

    load_tiles(0);
    load_tiles(1);

    for (int it = 0; it < nIter; it++) {
        if (it + 1 < nIter) asm volatile("cp.async.wait_group 1;\n");
        else                asm volatile("cp.async.wait_group 0;\n");
        __syncthreads();
        // issue next-next tile AFTER the barrier: its target stage (it+2)%3
        // equals (it-1)%3, which every warp has finished reading.
        if (it + 2 < nIter) load_tiles(it + 2);

        uint32_t sb = smemBase + (it % 3) * STAGE_BYTES;
        #pragma unroll
        for (int kk = 0; kk < 2; kk++) {
            const int kx = kk << 5;
            uint32_t ah[2][4], al[2][4];
            #pragma unroll
            for (int mi = 0; mi < 2; mi++) {
                LDSM4(ah[mi][0], ah[mi][1], ah[mi][2], ah[mi][3],
                      sb + (aoff[mi] ^ kx));
                LDSM4(al[mi][0], al[mi][1], al[mi][2], al[mi][3],
                      sb + 8192 + (aoff[mi] ^ kx));
            }
            #pragma unroll
            for (int np = 0; np < 4; np++) {
                uint32_t bh[4], bl[4];
                LDSM4(bh[0], bh[1], bh[2], bh[3], sb + 16384 + (boff[np] ^ kx));
                LDSM4(bl[0], bl[1], bl[2], bl[3], sb + 24576 + (boff[np] ^ kx));
                #pragma unroll
                for (int mi = 0; mi < 2; mi++) {
                    MMA_BF16(acc[mi][np*2],   ah[mi][0], ah[mi][1], ah[mi][2], ah[mi][3], bl[0], bl[1]);
                    MMA_BF16(acc[mi][np*2],   al[mi][0], al[mi][1], al[mi][2], al[mi][3], bh[0], bh[1]);
                    MMA_BF16(acc[mi][np*2],   ah[mi][0], ah[mi][1], ah[mi][2], ah[mi][3], bh[0], bh[1]);
                    MMA_BF16(acc[mi][np*2+1], ah[mi][0], ah[mi][1], ah[mi][2], ah[mi][3], bl[2], bl[3]);
                    MMA_BF16(acc[mi][np*2+1], al[mi][0], al[mi][1], al[mi][2], al[mi][3], bh[2], bh[3]);
                    MMA_BF16(acc[mi][np*2+1], ah[mi][0], ah[mi][1], ah[mi][2], ah[mi][3], bh[2], bh[3]);
                }
            }
        }
    }

    // epilogue
    const int g = lane >> 2, tq = lane & 3;
    #pragma unroll
    for (int mi = 0; mi < 2; mi++) {
        int r0 = row0 + warp_m * 32 + mi * 16 + g;
        #pragma unroll
        for (int ni = 0; ni < 8; ni++) {
            int c0 = col0 + warp_n * 64 + ni * 8 + tq * 2;
            if (c0 >= Nout) continue;
            float b0 = 0.f, b1 = 0.f;
            if (bias) { b0 = bias[c0]; b1 = bias[c0 + 1]; }
            float v0 = acc[mi][ni][0] + b0;
            float v1 = acc[mi][ni][1] + b1;
            float v2 = acc[mi][ni][2] + b0;
            float v3 = acc[mi][ni][3] + b1;
            if (act == 1) {
                v0 = fmaxf(v0, 0.f); v1 = fmaxf(v1, 0.f);
                v2 = fmaxf(v2, 0.f); v3 = fmaxf(v3, 0.f);
            }
            size_t o0 = (size_t)r0 * Nld + c0;
            size_t o1 = (size_t)(r0 + 8) * Nld + c0;
            if (C) {
                *(float2*)&C[o0] = make_float2(v0, v1);
                *(float2*)&C[o1] = make_float2(v2, v3);
            }
            if (Oh) {
                __nv_bfloat162 h0 = __floats2bfloat162_rn(v0, v1);
                __nv_bfloat162 h1 = __floats2bfloat162_rn(v2, v3);
                __nv_bfloat162 l0 = __floats2bfloat162_rn(v0 - __bfloat162float(h0.x),
                                                          v1 - __bfloat162float(h0.y));
                __nv_bfloat162 l1 = __floats2bfloat162_rn(v2 - __bfloat162float(h1.x),
                                                          v3 - __bfloat162float(h1.y));
                *(__nv_bfloat162*)(Oh + o0) = h0;
                *(__nv_bfloat162*)(Oh + o1) = h1;
                *(__nv_bfloat162*)(Ol + o0) = l0;
                *(__nv_bfloat162*)(Ol + o1) = l1;
            }
        }
    }
}

// ---------------- depthwise causal conv (k=4) + SiLU (+ bf16 split) --------
__global__ void conv_silu_kernel(const float* __restrict__ xz,
                                 const float* __restrict__ cw,
                                 const float* __restrict__ cb,
                                 float* __restrict__ u,
                                 __nv_bfloat16* __restrict__ uh,
                                 __nv_bfloat16* __restrict__ ul) {
    int idx = blockIdx.x * blockDim.x + threadIdx.x;
    int d   = idx & (D_INNER - 1);
    int tok = idx >> 8;
    int l   = tok & (LL - 1);
    float acc = cb[d];
    #pragma unroll
    for (int j = 0; j < 4; j++) {
        int tl = l - 3 + j;
        if (tl >= 0)
            acc = fmaf(cw[d * 4 + j], xz[(size_t)(tok - 3 + j) * (2*D_INNER) + d], acc);
    }
    float s = acc / (1.0f + __expf(-acc));
    u[idx] = s;
    __nv_bfloat16 h = __float2bfloat16(s);
    uh[idx] = h;
    ul[idx] = __float2bfloat16(s - __bfloat162float(h));
}

// ================= chunk-parallel selective scan =================
__global__ void scan1_kernel(const float* __restrict__ u,
                             const float* __restrict__ dbc,
                             const float* __restrict__ Wdt,
                             const float* __restrict__ bdt,
                             const float* __restrict__ A_log,
                             float* __restrict__ Sbuf,
                             float* __restrict__ Dbuf) {
    __shared__ float sR [SCH][8];
    __shared__ float sB [SCH][16];
    __shared__ float su [SCH][16];
    __shared__ float sdt[SCH][16];
    __shared__ float swt[8][16];
    __shared__ float sbd[16];
    int chunk = blockIdx.x, chg = blockIdx.y, b = blockIdx.z;
    int ch0 = chg * 16;
    int tid = threadIdx.x;
    int cl  = tid >> 4;
    int s   = tid & 15;
    int ch  = ch0 + cl;
    if (tid < 128) swt[tid >> 4][tid & 15] = Wdt[(tid >> 4) * D_INNER + ch0 + (tid & 15)];
    if (tid < 16)  sbd[tid] = bdt[ch0 + tid];
    float A = -__expf(A_log[ch * D_STATE + s]);
    float h = 0.0f, sum = 0.0f;
    size_t tokbase = (size_t)b * LL + (size_t)chunk * CLEN;
    __syncthreads();
    for (int t0 = 0; t0 < CLEN; t0 += SCH) {
        for (int i = tid; i < SCH * 8; i += 256) {
            int st = i >> 3, j = i & 7;
            sR[st][j] = dbc[(tokbase + t0 + st) * 40 + j];
        }
        for (int i = tid; i < SCH * 16; i += 256) {
            int st = i >> 4, j = i & 15;
            sB[st][j] = dbc[(tokbase + t0 + st) * 40 + 8 + j];
            su[st][j] = u  [(tokbase + t0 + st) * D_INNER + ch0 + j];
        }
        __syncthreads();
        for (int i = tid; i < SCH * 16; i += 256) {
            int st = i >> 4, j = i & 15;
            float a = sbd[j];
            #pragma unroll
            for (int jj = 0; jj < 8; jj++) a = fmaf(sR[st][jj], swt[jj][j], a);
            sdt[st][j] = (a > 20.0f) ? a : log1pf(__expf(a));
        }
        __syncthreads();
        #pragma unroll 4
        for (int i = 0; i < SCH; i++) {
            float dtv = sdt[i][cl];
            h = fmaf(__expf(dtv * A), h, dtv * su[i][cl] * sB[i][s]);
            sum += dtv;
        }
        __syncthreads();
    }
    size_t o = (((size_t)b * D_INNER + ch) * NCHUNK + chunk) * 16 + s;
    Sbuf[o] = h;
    if (s == 0) Dbuf[((size_t)b * D_INNER + ch) * NCHUNK + chunk] = sum;
}

__global__ void scanc_kernel(const float* __restrict__ A_log,
                             const float* __restrict__ Sbuf,
                             const float* __restrict__ Dbuf,
                             float* __restrict__ Hbuf) {
    int idx = blockIdx.x * 256 + threadIdx.x;
    int s  = idx & 15;
    int ch = (idx >> 4) & 255;
    int b  = idx >> 12;
    float A = -__expf(A_log[ch * D_STATE + s]);
    float h = 0.0f;
    size_t base = ((size_t)b * D_INNER + ch) * NCHUNK;
    #pragma unroll
    for (int c = 0; c < NCHUNK; c++) {
        Hbuf[(base + c) * 16 + s] = h;
        h = fmaf(__expf(A * Dbuf[base + c]), h, Sbuf[(base + c) * 16 + s]);
    }
}

__global__ void scan2_kernel(const float* __restrict__ u,
                             const float* __restrict__ dbc,
                             const float* __restrict__ xz,
                             const float* __restrict__ Wdt,
                             const float* __restrict__ bdt,
                             const float* __restrict__ A_log,
                             const float* __restrict__ Dskip,
                             const float* __restrict__ Hbuf,
                             __nv_bfloat16* __restrict__ yh,
                             __nv_bfloat16* __restrict__ yl) {
    __shared__ float sR [SCH][8];
    __shared__ float sB [SCH][16];
    __shared__ float sC [SCH][16];
    __shared__ float su [SCH][16];
    __shared__ float sz [SCH][16];
    __shared__ float sdt[SCH][16];
    __shared__ float sy [SCH][16];
    __shared__ float swt[8][16];
    __shared__ float sbd[16];
    int chunk = blockIdx.x, chg = blockIdx.y, b = blockIdx.z;
    int ch0 = chg * 16;
    int tid = threadIdx.x;
    int cl  = tid >> 4;
    int s   = tid & 15;
    int ch  = ch0 + cl;
    if (tid < 128) swt[tid >> 4][tid & 15] = Wdt[(tid >> 4) * D_INNER + ch0 + (tid & 15)];
    if (tid < 16)  sbd[tid] = bdt[ch0 + tid];
    float A  = -__expf(A_log[ch * D_STATE + s]);
    float Ds = Dskip[ch];
    float h  = Hbuf[(((size_t)b * D_INNER + ch) * NCHUNK + chunk) * 16 + s];
    size_t tokbase = (size_t)b * LL + (size_t)chunk * CLEN;
    __syncthreads();
    for (int t0 = 0; t0 < CLEN; t0 += SCH) {
        for (int i = tid; i < SCH * 8; i += 256) {
            int st = i >> 3, j = i & 7;
            sR[st][j] = dbc[(tokbase + t0 + st) * 40 + j];
        }
        for (int i = tid; i < SCH * 16; i += 256) {
            int st = i >> 4, j = i & 15;
            size_t tok = tokbase + t0 + st;
            sB[st][j] = dbc[tok * 40 + 8  + j];
            sC[st][j] = dbc[tok * 40 + 24 + j];
            su[st][j] = u  [tok * D_INNER + ch0 + j];
            sz[st][j] = xz [tok * (2*D_INNER) + D_INNER + ch0 + j];
        }
        __syncthreads();
        for (int i = tid; i < SCH * 16; i += 256) {
            int st = i >> 4, j = i & 15;
            float a = sbd[j];
            #pragma unroll
            for (int jj = 0; jj < 8; jj++) a = fmaf(sR[st][jj], swt[jj][j], a);
            sdt[st][j] = (a > 20.0f) ? a : log1pf(__expf(a));
        }
        __syncthreads();
        #pragma unroll 4
        for (int i = 0; i < SCH; i++) {
            float dtv = sdt[i][cl];
            float uv  = su [i][cl];
            h = fmaf(__expf(dtv * A), h, dtv * uv * sB[i][s]);
            float p = h * sC[i][s];
            p += __shfl_xor_sync(0xffffffffu, p, 8);
            p += __shfl_xor_sync(0xffffffffu, p, 4);
            p += __shfl_xor_sync(0xffffffffu, p, 2);
            p += __shfl_xor_sync(0xffffffffu, p, 1);
            if (s == 0) {
                float zv = sz[i][cl];
                float yv = p + uv * Ds;
                yv *= zv / (1.0f + __expf(-zv));
                sy[i][cl] = yv;
            }
        }
        __syncthreads();
        for (int i = tid; i < SCH * 16; i += 256) {
            int st = i >> 4, j = i & 15;
            float yv = sy[st][j];
            __nv_bfloat16 hh = __float2bfloat16(yv);
            __nv_bfloat16 lo = __float2bfloat16(yv - __bfloat162float(hh));
            size_t o = (tokbase + t0 + st) * D_INNER + ch0 + j;
            yh[o] = hh;
            yl[o] = lo;
        }
        __syncthreads();
    }
}

// ---------------- host launcher ----------------
extern "C" void kernel_launch(void* const* d_in, const int* in_sizes, int n_in,
                              void* d_out, int out_size) {
    const int*   tokens  = (const int*)  d_in[0];
    const float* emb     = (const float*)d_in[1];
    const float* ln_w    = (const float*)d_in[2];
    const float* ln_b    = (const float*)d_in[3];
    const float* W_in    = (const float*)d_in[4];
    const float* conv_w  = (const float*)d_in[5];
    const float* conv_b  = (const float*)d_in[6];
    const float* W_xproj = (const float*)d_in[7];
    const float* W_dt    = (const float*)d_in[8];
    const float* b_dt    = (const float*)d_in[9];
    const float* A_log   = (const float*)d_in[10];
    const float* D_skip  = (const float*)d_in[11];
    const float* W_out   = (const float*)d_in[12];
    const float* W1      = (const float*)d_in[13];
    const float* b1      = (const float*)d_in[14];
    const float* W2      = (const float*)d_in[15];
    const float* b2      = (const float*)d_in[16];
    float* out = (float*)d_out;

    float *x, *xz, *u, *dbc, *S, *Hc, *Dc;
    __nv_bfloat16 *uh, *ul, *ah, *al, *xh, *xl, *bh, *bl;
    cudaGetSymbolAddress((void**)&x,   g_x);
    cudaGetSymbolAddress((void**)&xz,  g_xz);
    cudaGetSymbolAddress((void**)&u,   g_u);
    cudaGetSymbolAddress((void**)&dbc, g_db);
    cudaGetSymbolAddress((void**)&S,   g_S);
    cudaGetSymbolAddress((void**)&Hc,  g_Hc);
    cudaGetSymbolAddress((void**)&Dc,  g_Dc);
    cudaGetSymbolAddress((void**)&uh,  g_uh);
    cudaGetSymbolAddress((void**)&ul,  g_ul);
    cudaGetSymbolAddress((void**)&ah,  g_ah);
    cudaGetSymbolAddress((void**)&al,  g_al);
    cudaGetSymbolAddress((void**)&xh,  g_xh);
    cudaGetSymbolAddress((void**)&xl,  g_xl);
    cudaGetSymbolAddress((void**)&bh,  g_bh);
    cudaGetSymbolAddress((void**)&bl,  g_bl);

    cudaFuncSetAttribute(mma_bf16_kernel,
                         cudaFuncAttributeMaxDynamicSharedMemorySize, MMA_SMEM);

    embed_kernel<<<(NTOK * 32) / 256, 256>>>(tokens, emb, x);

    for (int l = 0; l < N_LAYERS; l++) {
        const float* lw  = ln_w    + l * D_MODEL;
        const float* lb  = ln_b    + l * D_MODEL;
        const float* wi  = W_in    + (size_t)l * D_MODEL * 2 * D_INNER;
        const float* cw  = conv_w  + (size_t)l * D_INNER * D_CONV;
        const float* cb  = conv_b  + (size_t)l * D_INNER;
        const float* wx  = W_xproj + (size_t)l * D_INNER * 40;
        const float* wd  = W_dt    + (size_t)l * DT_RANK * D_INNER;
        const float* bd  = b_dt    + (size_t)l * D_INNER;
        const float* alog= A_log   + (size_t)l * D_INNER * D_STATE;
        const float* dsk = D_skip  + (size_t)l * D_INNER;
        const float* wo  = W_out   + (size_t)l * D_INNER * D_MODEL;

        ln_split_kernel<<<NTOK / 8, dim3(32, 8)>>>(x, lw, lb, ah, al);
        splitB_kernel<<<dim3(512 / 32, 128 / 32), dim3(32, 8)>>>(wi, bh, bl, 128, 512);
        // xz = ln @ W_in  [NTOK x 512], K=128
        mma_bf16_kernel<<<dim3(4, NTOK / 128), 256, MMA_SMEM>>>(
            ah, al, bh, bl, nullptr, xz, nullptr, nullptr, NTOK, 512, 512, 128, 0);
        conv_silu_kernel<<<NTOK * D_INNER / 256, 256>>>(xz, cw, cb, u, uh, ul);
        // dbc = u @ W_xproj  [NTOK x 40], K=256  (N padded to 128, writes guarded)
        splitB_kernel<<<dim3(128 / 32, 256 / 32), dim3(32, 8)>>>(wx, bh, bl, 256, 40);
        mma_bf16_kernel<<<dim3(1, NTOK / 128), 256, MMA_SMEM>>>(
            uh, ul, bh, bl, nullptr, dbc, nullptr, nullptr, NTOK, 40, 40, 256, 0);
        // chunk-parallel scan (dt fused)
        scan1_kernel<<<dim3(NCHUNK, 16, BB), 256>>>(u, dbc, wd, bd, alog, S, Dc);
        scanc_kernel<<<BB * 4096 / 256, 256>>>(alog, S, Dc, Hc);
        scan2_kernel<<<dim3(NCHUNK, 16, BB), 256>>>(u, dbc, xz, wd, bd, alog,
                                                    dsk, Hc, ah, al);
        // x = y @ W_out  [NTOK x 128], K=256  (+ split x for head)
        splitB_kernel<<<dim3(128 / 32, 256 / 32), dim3(32, 8)>>>(wo, bh, bl, 256, 128);
        mma_bf16_kernel<<<dim3(1, NTOK / 128), 256, MMA_SMEM>>>(
            ah, al, bh, bl, nullptr, x, xh, xl, NTOK, 128, 128, 256, 0);
    }

    // head: h1 = relu(x @ W1 + b1) -> split bf16 only
    splitB_kernel<<<dim3(512 / 32, 128 / 32), dim3(32, 8)>>>(W1, bh, bl, 128, 512);
    mma_bf16_kernel<<<dim3(4, NTOK / 128), 256, MMA_SMEM>>>(
        xh, xl, bh, bl, b1, nullptr, ah, al, NTOK, 512, 512, 128, 1);
    // out = h1 @ W2 + b2
    splitB_kernel<<<dim3(VOCAB / 32, 512 / 32), dim3(32, 8)>>>(W2, bh, bl, 512, VOCAB);
    mma_bf16_kernel<<<dim3(VOCAB / 128, NTOK / 128), 256, MMA_SMEM>>>(
        ah, al, bh, bl, b2, out, nullptr, nullptr, NTOK, VOCAB, VOCAB, 512, 0);
}